// round 1
// baseline (speedup 1.0000x reference)
#include <cuda_runtime.h>
#include <math.h>

#define Bz   4
#define Nn   8192
#define Cc   32
#define Kk   16
#define Hh   64
#define OUTC 128
#define CE   36                 // C+4
#define S_TOT (Bz*Nn*Kk)        // 524288
#define P_TOT (Bz*Nn)           // 32768

// ---------------- scratch (static device memory; allocation-free) -------------
__device__ float g_x  [S_TOT*Hh];   // lse pre-BN y, then post-BN/relu x (in place)
__device__ float g_z  [S_TOT*Hh];   // pre-BN hidden of att_pool score MLP
__device__ float g_g  [P_TOT*Hh];   // pre-BN pooled-MLP output
__device__ float g_agg[P_TOT*OUTC]; // concat(f1,f2)
__device__ float g_h1 [P_TOT*OUTC];
__device__ float g_h2 [P_TOT*OUTC];
__device__ int   g_idx[S_TOT];
__device__ float d_stats[8*256];    // per-stage [sum(nch), sumsq(nch)]
__device__ float d_mr  [8*256];     // per-stage mean at [0..), rstd at [128..)

__global__ void zero_stats_kernel() {
    int t = blockIdx.x*256 + threadIdx.x;
    if (t < 8*256) d_stats[t] = 0.f;
}

// ---------------- KNN: brute force top-16, register sorted list ---------------
#define KNN_T    64
#define KNN_TILE 256
__global__ void knn_kernel(const float* __restrict__ xyz) {
    int b = blockIdx.y;
    int n = blockIdx.x*KNN_T + threadIdx.x;
    const float* xb = xyz + b*Nn*3;
    float qx = xb[n*3+0], qy = xb[n*3+1], qz = xb[n*3+2];
    float bd[16]; int bi[16];
#pragma unroll
    for (int t=0;t<16;t++){ bd[t]=3.4e38f; bi[t]=0; }
    __shared__ float4 sp[KNN_TILE];
    for (int tile=0; tile<Nn; tile+=KNN_TILE) {
        __syncthreads();
        for (int t=threadIdx.x; t<KNN_TILE; t+=KNN_T) {
            int j = tile + t;
            sp[t] = make_float4(xb[j*3+0], xb[j*3+1], xb[j*3+2], 0.f);
        }
        __syncthreads();
#pragma unroll 8
        for (int jj=0; jj<KNN_TILE; jj++) {
            float4 c = sp[jj];
            float dx=qx-c.x, dy=qy-c.y, dz=qz-c.z;
            float d = dx*dx; d = fmaf(dy,dy,d); d = fmaf(dz,dz,d);
            if (d < bd[15]) {               // strict < keeps earlier index on tie (stable)
                bd[15]=d; bi[15]=tile+jj;
#pragma unroll
                for (int t=15;t>0;t--) {
                    if (bd[t] < bd[t-1]) {
                        float td=bd[t]; bd[t]=bd[t-1]; bd[t-1]=td;
                        int   ti=bi[t]; bi[t]=bi[t-1]; bi[t-1]=ti;
                    }
                }
            }
        }
    }
    int base = (b*Nn + n)*Kk;
#pragma unroll
    for (int t=0;t<16;t++) g_idx[base+t] = bi[t];
}

// ---------------- finalize BN stats -> mean/rstd ------------------------------
__global__ void finalize_kernel(int slot, float inv_cnt, int nch) {
    int o = threadIdx.x;
    if (o < nch) {
        float m = d_stats[slot*256 + o] * inv_cnt;
        float v = d_stats[slot*256 + nch + o] * inv_cnt - m*m;
        d_mr[slot*256 + o]       = m;
        d_mr[slot*256 + 128 + o] = rsqrtf(v + 1e-5f);
    }
}

// ---------------- LSE: enc = [rel(3),dist(1),nbr_f(32)] @ w  (+stats) ---------
#define LSE_GRID 1024
#define LSE_ITER 128
__global__ void lse_kernel(const float* __restrict__ xyz, const float* __restrict__ feat,
                           const float* __restrict__ w, int slot) {
    __shared__ float wT[CE*Hh];     // wT[c*64+o] = w[o*36+c]
    __shared__ float enc[4][CE];
    int tid = threadIdx.x;          // 256 = 4 samples x 64 channels
    int so = tid >> 6, o = tid & 63;
    for (int t=tid; t<CE*Hh; t+=256) { int oo=t/CE, cc=t-oo*CE; wT[cc*Hh+oo]=w[t]; }
    float asum=0.f, asq=0.f;
    __syncthreads();
    for (int it=0; it<LSE_ITER; it++) {
        int s = (blockIdx.x*LSE_ITER + it)*4 + so;
        int b = s >> 17;            // N*K = 131072
        int n = (s >> 4) & (Nn-1);
        int j = g_idx[s];
        if (o >= 4 && o < CE) {
            enc[so][o] = feat[(b*Nn + j)*Cc + (o-4)];
        } else if (o == 0) {
            const float* pj = &xyz[(b*Nn + j)*3];
            const float* pn = &xyz[(b*Nn + n)*3];
            float dx=pj[0]-pn[0], dy=pj[1]-pn[1], dz=pj[2]-pn[2];
            enc[so][0]=dx; enc[so][1]=dy; enc[so][2]=dz;
            float dd = dx*dx; dd=fmaf(dy,dy,dd); dd=fmaf(dz,dz,dd);
            enc[so][3] = sqrtf(fmaxf(dd, 1e-12f));
        }
        __syncthreads();
        float acc = 0.f;
#pragma unroll
        for (int c=0;c<CE;c++) acc = fmaf(enc[so][c], wT[c*Hh+o], acc);
        g_x[(size_t)s*Hh + o] = acc;
        asum += acc; asq = fmaf(acc, acc, asq);
        __syncthreads();
    }
    __shared__ float rs[256], rq[256];
    rs[tid]=asum; rq[tid]=asq;
    __syncthreads();
    if (so == 0) {
        float a = rs[o]+rs[64+o]+rs[128+o]+rs[192+o];
        float q = rq[o]+rq[64+o]+rq[128+o]+rq[192+o];
        atomicAdd(&d_stats[slot*256 + o],      a);
        atomicAdd(&d_stats[slot*256 + 64 + o], q);
    }
}

// ------- x = relu(bn(y)) in place; z = x @ sw1 (+stats) -----------------------
__global__ void xz_kernel(const float* __restrict__ sw1, int slot_y, int slot_z) {
    __shared__ float wT[Hh*Hh];     // wT[c*64+o] = sw1[o*64+c]
    __shared__ float xs[4][Hh];
    int tid = threadIdx.x;          // 256 = 4 samples x 64 channels
    int so = tid >> 6, o = tid & 63;
    for (int t=tid; t<Hh*Hh; t+=256) { int oo=t>>6, cc=t&63; wT[cc*Hh+oo]=sw1[t]; }
    float my = d_mr[slot_y*256 + o], ry = d_mr[slot_y*256 + 128 + o];
    float asum=0.f, asq=0.f;
    __syncthreads();
    for (int it=0; it<LSE_ITER; it++) {
        int s = (blockIdx.x*LSE_ITER + it)*4 + so;
        float xv = fmaxf((g_x[(size_t)s*Hh + o] - my)*ry, 0.f);
        g_x[(size_t)s*Hh + o] = xv;
        xs[so][o] = xv;
        __syncthreads();
        float z = 0.f;
#pragma unroll
        for (int c=0;c<Hh;c++) z = fmaf(xs[so][c], wT[c*Hh+o], z);
        g_z[(size_t)s*Hh + o] = z;
        asum += z; asq = fmaf(z, z, asq);
        __syncthreads();
    }
    __shared__ float rs[256], rq[256];
    rs[tid]=asum; rq[tid]=asq;
    __syncthreads();
    if (so == 0) {
        float a = rs[o]+rs[64+o]+rs[128+o]+rs[192+o];
        float q = rq[o]+rq[64+o]+rq[128+o]+rq[192+o];
        atomicAdd(&d_stats[slot_z*256 + o],      a);
        atomicAdd(&d_stats[slot_z*256 + 64 + o], q);
    }
}

// ------- attentive pool: scores from bn(z), softmax over k, feat@mw (+stats) --
#define POOL_GRID 512
#define POOL_ITER 32
__global__ void pool_kernel(const float* __restrict__ sw2, const float* __restrict__ sb2,
                            const float* __restrict__ mw, int slot_z, int slot_g) {
    __shared__ float mwT[Hh*Hh];    // mwT[c*64+o] = mw[o*64+c]
    __shared__ float zs[2][Kk][68]; // padded vs bank conflicts
    __shared__ float xs[2][Kk][64];
    __shared__ float sc[2][Kk];
    __shared__ float featS[2][Hh];
    __shared__ float mzS[64], rzS[64], sw2S[64];
    int tid = threadIdx.x;          // 128 = 2 points x 64 channels
    int pp = tid >> 6, o = tid & 63;
    for (int t=tid; t<Hh*Hh; t+=128) { int oo=t>>6, cc=t&63; mwT[cc*Hh+oo]=mw[t]; }
    if (tid < 64) {
        mzS[tid] = d_mr[slot_z*256 + tid];
        rzS[tid] = d_mr[slot_z*256 + 128 + tid];
        sw2S[tid]= sw2[tid];
    }
    float sb = sb2[0];
    int kq = (tid>>2)&15, cg = tid&3, pq = tid>>6;   // score-phase layout
    float gsum=0.f, gsq=0.f;
    __syncthreads();
    for (int it=0; it<POOL_ITER; it++) {
        int p0 = (blockIdx.x*POOL_ITER + it)*2;
        const float* zsrc = &g_z[(size_t)p0*Kk*Hh];
        const float* xsrc = &g_x[(size_t)p0*Kk*Hh];
        for (int t=tid; t<2*Kk*Hh; t+=128) {
            int pt = t>>10, k2 = (t>>6)&15, c2 = t&63;
            zs[pt][k2][c2] = zsrc[t];
            xs[pt][k2][c2] = xsrc[t];
        }
        __syncthreads();
        // scores: s[k] = sb2 + sum_c relu(bn(z)) * sw2  (128 threads, 16c each)
        float sacc = 0.f;
#pragma unroll
        for (int cc=0; cc<16; cc++) {
            int c = cg*16 + cc;
            sacc += fmaxf((zs[pq][kq][c]-mzS[c])*rzS[c], 0.f) * sw2S[c];
        }
        sacc += __shfl_xor_sync(0xffffffffu, sacc, 1, 4);
        sacc += __shfl_xor_sync(0xffffffffu, sacc, 2, 4);
        if (cg == 0) sc[pq][kq] = sacc + sb;
        __syncthreads();
        // softmax over k + weighted pool, per (point, channel)
        float mx = sc[pp][0];
#pragma unroll
        for (int k=1;k<16;k++) mx = fmaxf(mx, sc[pp][k]);
        float pk[16], den=0.f;
#pragma unroll
        for (int k=0;k<16;k++){ pk[k]=__expf(sc[pp][k]-mx); den+=pk[k]; }
        float inv = 1.f/den;
        float feat = 0.f;
#pragma unroll
        for (int k=0;k<16;k++) feat = fmaf(xs[pp][k][o], pk[k], feat);
        feat *= inv;
        featS[pp][o] = feat;
        __syncthreads();
        float gv = 0.f;
#pragma unroll
        for (int c=0;c<Hh;c++) gv = fmaf(featS[pp][c], mwT[c*Hh+o], gv);
        g_g[(size_t)(p0+pp)*Hh + o] = gv;
        gsum += gv; gsq = fmaf(gv, gv, gsq);
        __syncthreads();
    }
    __shared__ float r1[128], r2[128];
    r1[tid]=gsum; r2[tid]=gsq;
    __syncthreads();
    if (tid < 64) {
        atomicAdd(&d_stats[slot_g*256 + tid],      r1[tid]+r1[tid+64]);
        atomicAdd(&d_stats[slot_g*256 + 64 + tid], r2[tid]+r2[tid+64]);
    }
}

// ------- f = relu(bn(g)) -> agg[:, broff..broff+64) ---------------------------
__global__ void apply_f_kernel(int slot_g, int broff) {
    int t = blockIdx.x*256 + threadIdx.x;    // P_TOT*64
    int p = t >> 6, o = t & 63;
    g_agg[(size_t)p*OUTC + broff + o] =
        fmaxf((g_g[t] - d_mr[slot_g*256 + o]) * d_mr[slot_g*256 + 128 + o], 0.f);
}

// ------- DRB matmul: out = (opt relu(bn(src))) @ w  (+stats) ------------------
#define DRB_GRID 512
#define DRB_ITER 32
__global__ void drb_mm_kernel(const float* __restrict__ w, int mode) {
    extern __shared__ float sh[];
    float* wT   = sh;               // [128][128] transposed
    float* rows = sh + OUTC*OUTC;   // 2 x 128
    const float* src = (mode==0) ? g_agg : g_h1;
    float*       dst = (mode==0) ? g_h1  : g_h2;
    int slot_in  = (mode==0) ? -1 : 6;
    int slot_out = (mode==0) ?  6 : 7;
    int tid = threadIdx.x;          // 128
    for (int t=tid; t<OUTC*OUTC; t+=128) { int oo=t>>7, cc=t&127; wT[cc*OUTC+oo]=w[t]; }
    float mi=0.f, ri=1.f;
    if (slot_in >= 0) { mi = d_mr[slot_in*256 + tid]; ri = d_mr[slot_in*256 + 128 + tid]; }
    float asum=0.f, asq=0.f;
    __syncthreads();
    for (int it=0; it<DRB_ITER; it++) {
        int s0 = (blockIdx.x*DRB_ITER + it)*2;
        float v0 = src[(size_t)s0*OUTC + tid];
        float v1 = src[(size_t)(s0+1)*OUTC + tid];
        if (slot_in >= 0) { v0 = fmaxf((v0-mi)*ri, 0.f); v1 = fmaxf((v1-mi)*ri, 0.f); }
        rows[tid] = v0; rows[OUTC+tid] = v1;
        __syncthreads();
        float a0=0.f, a1=0.f;
#pragma unroll 16
        for (int c=0;c<OUTC;c++) {
            float wv = wT[c*OUTC + tid];
            a0 = fmaf(rows[c],      wv, a0);
            a1 = fmaf(rows[OUTC+c], wv, a1);
        }
        dst[(size_t)s0*OUTC + tid]     = a0;
        dst[(size_t)(s0+1)*OUTC + tid] = a1;
        asum += a0 + a1;
        asq  = fmaf(a0,a0,asq); asq = fmaf(a1,a1,asq);
        __syncthreads();
    }
    atomicAdd(&d_stats[slot_out*256 + tid],       asum);
    atomicAdd(&d_stats[slot_out*256 + 128 + tid], asq);
}

// ------- out = relu(bn(h2) + agg) ---------------------------------------------
__global__ void final_kernel(float* __restrict__ out) {
    int t = blockIdx.x*256 + threadIdx.x;    // P_TOT*128
    int o = t & 127;
    out[t] = fmaxf((g_h2[t] - d_mr[7*256 + o]) * d_mr[7*256 + 128 + o] + g_agg[t], 0.f);
}

// ------------------------------ launch ----------------------------------------
extern "C" void kernel_launch(void* const* d_in, const int* in_sizes, int n_in,
                              void* d_out, int out_size) {
    const float* xyz     = (const float*)d_in[0];
    const float* feat    = (const float*)d_in[1];
    const float* w_lse1  = (const float*)d_in[2];
    const float* w_lse2  = (const float*)d_in[3];
    const float* ap1_sw1 = (const float*)d_in[4];
    const float* ap1_sw2 = (const float*)d_in[5];
    const float* ap1_sb2 = (const float*)d_in[6];
    const float* ap1_mw  = (const float*)d_in[7];
    const float* ap2_sw1 = (const float*)d_in[8];
    const float* ap2_sw2 = (const float*)d_in[9];
    const float* ap2_sb2 = (const float*)d_in[10];
    const float* ap2_mw  = (const float*)d_in[11];
    const float* drb_w1  = (const float*)d_in[12];
    const float* drb_w2  = (const float*)d_in[13];
    float* out = (float*)d_out;

    size_t dsm = (size_t)(OUTC*OUTC + 2*OUTC) * sizeof(float);   // 66.5 KB
    cudaFuncSetAttribute(drb_mm_kernel, cudaFuncAttributeMaxDynamicSharedMemorySize, (int)dsm);

    const float inv_S = 1.f/(float)S_TOT;
    const float inv_P = 1.f/(float)P_TOT;

    zero_stats_kernel<<<8,256>>>();
    knn_kernel<<<dim3(Nn/KNN_T, Bz), KNN_T>>>(xyz);

    // branch 1
    lse_kernel<<<LSE_GRID,256>>>(xyz, feat, w_lse1, 0);
    finalize_kernel<<<1,128>>>(0, inv_S, 64);
    xz_kernel<<<LSE_GRID,256>>>(ap1_sw1, 0, 1);
    finalize_kernel<<<1,128>>>(1, inv_S, 64);
    pool_kernel<<<POOL_GRID,128>>>(ap1_sw2, ap1_sb2, ap1_mw, 1, 2);
    finalize_kernel<<<1,128>>>(2, inv_P, 64);
    apply_f_kernel<<<P_TOT*64/256,256>>>(2, 0);

    // branch 2
    lse_kernel<<<LSE_GRID,256>>>(xyz, feat, w_lse2, 3);
    finalize_kernel<<<1,128>>>(3, inv_S, 64);
    xz_kernel<<<LSE_GRID,256>>>(ap2_sw1, 3, 4);
    finalize_kernel<<<1,128>>>(4, inv_S, 64);
    pool_kernel<<<POOL_GRID,128>>>(ap2_sw2, ap2_sb2, ap2_mw, 4, 5);
    finalize_kernel<<<1,128>>>(5, inv_P, 64);
    apply_f_kernel<<<P_TOT*64/256,256>>>(5, 64);

    // dilated residual block
    drb_mm_kernel<<<DRB_GRID,128,dsm>>>(drb_w1, 0);
    finalize_kernel<<<1,128>>>(6, inv_P, 128);
    drb_mm_kernel<<<DRB_GRID,128,dsm>>>(drb_w2, 1);
    finalize_kernel<<<1,128>>>(7, inv_P, 128);
    final_kernel<<<P_TOT*OUTC/256,256>>>(out);
}

// round 2
// speedup vs baseline: 1.4936x; 1.4936x over previous
#include <cuda_runtime.h>
#include <math.h>

#define Bz   4
#define Nn   8192
#define Cc   32
#define Kk   16
#define Hh   64
#define OUTC 128
#define CE   36
#define S_TOT (Bz*Nn*Kk)        // 524288
#define P_TOT (Bz*Nn)           // 32768

// ---------------- scratch -----------------------------------------------------
__device__ float g_x  [S_TOT*Hh];   // lse pre-BN y (raw; BN applied on read)
__device__ float g_z  [S_TOT*Hh];   // pre-BN hidden of att_pool score MLP
__device__ float g_g  [P_TOT*Hh];
__device__ float g_agg[P_TOT*OUTC];
__device__ float g_h1 [P_TOT*OUTC];
__device__ float g_h2 [P_TOT*OUTC];
__device__ int   g_idx[S_TOT];
__device__ float d_stats[8*256];
__device__ float d_mr  [8*256];     // mean at [0..), rstd at [128..)

__global__ void zero_stats_kernel() {
    int t = blockIdx.x*256 + threadIdx.x;
    if (t < 8*256) d_stats[t] = 0.f;
}

// ---------------- KNN ---------------------------------------------------------
#define KNN_T    128
#define KNN_TILE 512
__global__ void knn_kernel(const float* __restrict__ xyz) {
    int b = blockIdx.y;
    int n = blockIdx.x*KNN_T + threadIdx.x;
    const float* xb = xyz + b*Nn*3;
    float qx = xb[n*3+0], qy = xb[n*3+1], qz = xb[n*3+2];
    float m2x = -2.f*qx, m2y = -2.f*qy, m2z = -2.f*qz;
    float bd[16]; int bi[16];
#pragma unroll
    for (int t=0;t<16;t++){ bd[t]=3.4e38f; bi[t]=0; }
    __shared__ float4 sp[KNN_TILE];
    for (int tile=0; tile<Nn; tile+=KNN_TILE) {
        __syncthreads();
        for (int t=threadIdx.x; t<KNN_TILE; t+=KNN_T) {
            int j = tile + t;
            float x = xb[j*3+0], y = xb[j*3+1], z = xb[j*3+2];
            float w = x*x; w = fmaf(y,y,w); w = fmaf(z,z,w);
            sp[t] = make_float4(x, y, z, w);
        }
        __syncthreads();
#pragma unroll 8
        for (int jj=0; jj<KNN_TILE; jj++) {
            float4 c = sp[jj];
            // monotone transform of squared distance: |c|^2 - 2 q.c
            float d = fmaf(c.x, m2x, fmaf(c.y, m2y, fmaf(c.z, m2z, c.w)));
            if (d < bd[15]) {
                bd[15]=d; bi[15]=tile+jj;
#pragma unroll
                for (int t=15;t>0;t--) {
                    if (bd[t] < bd[t-1]) {
                        float td=bd[t]; bd[t]=bd[t-1]; bd[t-1]=td;
                        int   ti=bi[t]; bi[t]=bi[t-1]; bi[t-1]=ti;
                    }
                }
            }
        }
    }
    int base = (b*Nn + n)*Kk;
#pragma unroll
    for (int t=0;t<16;t++) g_idx[base+t] = bi[t];
}

// ---------------- finalize BN stats -------------------------------------------
__global__ void finalize_kernel(int slot, float inv_cnt, int nch) {
    int o = threadIdx.x;
    if (o < nch) {
        float m = d_stats[slot*256 + o] * inv_cnt;
        float v = d_stats[slot*256 + nch + o] * inv_cnt - m*m;
        d_mr[slot*256 + o]       = m;
        d_mr[slot*256 + 128 + o] = rsqrtf(v + 1e-5f);
    }
}

// ---------------- LSE: enc[36] @ w -> g_x (+stats), register-tiled ------------
#define LSE_TILES 16
__global__ void lse_kernel(const float* __restrict__ xyz, const float* __restrict__ feat,
                           const float* __restrict__ w, int slot) {
    __shared__ float wT[CE*Hh];     // [c][o]
    __shared__ float encT[CE][68];  // [c][s]
    __shared__ float ss[Hh], sq[Hh];
    int tid = threadIdx.x;          // 256
    int ts = tid & 15, to = tid >> 4;
    int s0 = ts*4, o0 = to*4;
    int sl = tid >> 2, gq = tid & 3;
    for (int t=tid; t<CE*Hh; t+=256) { int oo=t/CE, cc=t-oo*CE; wT[cc*Hh+oo]=w[t]; }
    if (tid < Hh) { ss[tid]=0.f; sq[tid]=0.f; }
    float stS[4]={0,0,0,0}, stQ[4]={0,0,0,0};
    __syncthreads();
    for (int tile=0; tile<LSE_TILES; tile++) {
        int base = (blockIdx.x*LSE_TILES + tile)*64;
        {   // build encoded tile (4 threads per sample)
            int s = base + sl;
            int b = s >> 17;
            int n = (s >> 4) & (Nn-1);
            int j = g_idx[s];
            const float4* fp = (const float4*)(feat + ((size_t)(b*Nn + j))*Cc + gq*8);
            float4 v0 = fp[0], v1 = fp[1];
            int c0 = 4 + gq*8;
            encT[c0+0][sl]=v0.x; encT[c0+1][sl]=v0.y; encT[c0+2][sl]=v0.z; encT[c0+3][sl]=v0.w;
            encT[c0+4][sl]=v1.x; encT[c0+5][sl]=v1.y; encT[c0+6][sl]=v1.z; encT[c0+7][sl]=v1.w;
            if (gq == 0) {
                const float* pj = xyz + ((size_t)(b*Nn + j))*3;
                const float* pn = xyz + ((size_t)(b*Nn + n))*3;
                float dx=pj[0]-pn[0], dy=pj[1]-pn[1], dz=pj[2]-pn[2];
                encT[0][sl]=dx; encT[1][sl]=dy; encT[2][sl]=dz;
                float dd = dx*dx; dd=fmaf(dy,dy,dd); dd=fmaf(dz,dz,dd);
                encT[3][sl] = sqrtf(fmaxf(dd, 1e-12f));
            }
        }
        __syncthreads();
        float acc[4][4] = {};
#pragma unroll
        for (int k=0;k<CE;k++) {
            float4 ev = *(const float4*)&encT[k][s0];
            float4 wv = *(const float4*)&wT[k*Hh + o0];
            acc[0][0]=fmaf(ev.x,wv.x,acc[0][0]); acc[0][1]=fmaf(ev.x,wv.y,acc[0][1]);
            acc[0][2]=fmaf(ev.x,wv.z,acc[0][2]); acc[0][3]=fmaf(ev.x,wv.w,acc[0][3]);
            acc[1][0]=fmaf(ev.y,wv.x,acc[1][0]); acc[1][1]=fmaf(ev.y,wv.y,acc[1][1]);
            acc[1][2]=fmaf(ev.y,wv.z,acc[1][2]); acc[1][3]=fmaf(ev.y,wv.w,acc[1][3]);
            acc[2][0]=fmaf(ev.z,wv.x,acc[2][0]); acc[2][1]=fmaf(ev.z,wv.y,acc[2][1]);
            acc[2][2]=fmaf(ev.z,wv.z,acc[2][2]); acc[2][3]=fmaf(ev.z,wv.w,acc[2][3]);
            acc[3][0]=fmaf(ev.w,wv.x,acc[3][0]); acc[3][1]=fmaf(ev.w,wv.y,acc[3][1]);
            acc[3][2]=fmaf(ev.w,wv.z,acc[3][2]); acc[3][3]=fmaf(ev.w,wv.w,acc[3][3]);
        }
#pragma unroll
        for (int si=0; si<4; si++) {
            float4 r = make_float4(acc[si][0],acc[si][1],acc[si][2],acc[si][3]);
            *(float4*)&g_x[(size_t)(base+s0+si)*Hh + o0] = r;
            stS[0]+=r.x; stS[1]+=r.y; stS[2]+=r.z; stS[3]+=r.w;
            stQ[0]=fmaf(r.x,r.x,stQ[0]); stQ[1]=fmaf(r.y,r.y,stQ[1]);
            stQ[2]=fmaf(r.z,r.z,stQ[2]); stQ[3]=fmaf(r.w,r.w,stQ[3]);
        }
        __syncthreads();
    }
#pragma unroll
    for (int j=0;j<4;j++){ atomicAdd(&ss[o0+j], stS[j]); atomicAdd(&sq[o0+j], stQ[j]); }
    __syncthreads();
    if (tid < Hh) {
        atomicAdd(&d_stats[slot*256 + tid],      ss[tid]);
        atomicAdd(&d_stats[slot*256 + 64 + tid], sq[tid]);
    }
}

// ------- z = relu(bn(y)) @ sw1 (+stats), register-tiled ------------------------
#define XZ_TILES 16
__global__ void xz_kernel(const float* __restrict__ sw1, int slot_y, int slot_z) {
    __shared__ float w2[Hh*Hh];     // [k][o]
    __shared__ float xT[Hh][68];    // [k][s]
    __shared__ float mS[Hh], rS[Hh], ss[Hh], sq[Hh];
    int tid = threadIdx.x;          // 256
    int ts = tid & 15, to = tid >> 4;
    int s0 = ts*4, o0 = to*4;
    for (int t=tid; t<Hh*Hh; t+=256) { int oo=t>>6, kk=t&63; w2[kk*Hh+oo]=sw1[t]; }
    if (tid < 64) {
        mS[tid]=d_mr[slot_y*256+tid]; rS[tid]=d_mr[slot_y*256+128+tid];
        ss[tid]=0.f; sq[tid]=0.f;
    }
    float stS[4]={0,0,0,0}, stQ[4]={0,0,0,0};
    __syncthreads();
    for (int tile=0; tile<XZ_TILES; tile++) {
        int base = (blockIdx.x*XZ_TILES + tile)*64;
        for (int t=tid; t<64*16; t+=256) {
            int s = t>>4, q = t&15;
            float4 v = ((const float4*)(g_x + (size_t)(base+s)*Hh))[q];
            int c = q*4;
            v.x = fmaxf((v.x-mS[c  ])*rS[c  ], 0.f);
            v.y = fmaxf((v.y-mS[c+1])*rS[c+1], 0.f);
            v.z = fmaxf((v.z-mS[c+2])*rS[c+2], 0.f);
            v.w = fmaxf((v.w-mS[c+3])*rS[c+3], 0.f);
            xT[c][s]=v.x; xT[c+1][s]=v.y; xT[c+2][s]=v.z; xT[c+3][s]=v.w;
        }
        __syncthreads();
        float acc[4][4] = {};
#pragma unroll 16
        for (int k=0;k<Hh;k++) {
            float4 xv = *(const float4*)&xT[k][s0];
            float4 wv = *(const float4*)&w2[k*Hh + o0];
            acc[0][0]=fmaf(xv.x,wv.x,acc[0][0]); acc[0][1]=fmaf(xv.x,wv.y,acc[0][1]);
            acc[0][2]=fmaf(xv.x,wv.z,acc[0][2]); acc[0][3]=fmaf(xv.x,wv.w,acc[0][3]);
            acc[1][0]=fmaf(xv.y,wv.x,acc[1][0]); acc[1][1]=fmaf(xv.y,wv.y,acc[1][1]);
            acc[1][2]=fmaf(xv.y,wv.z,acc[1][2]); acc[1][3]=fmaf(xv.y,wv.w,acc[1][3]);
            acc[2][0]=fmaf(xv.z,wv.x,acc[2][0]); acc[2][1]=fmaf(xv.z,wv.y,acc[2][1]);
            acc[2][2]=fmaf(xv.z,wv.z,acc[2][2]); acc[2][3]=fmaf(xv.z,wv.w,acc[2][3]);
            acc[3][0]=fmaf(xv.w,wv.x,acc[3][0]); acc[3][1]=fmaf(xv.w,wv.y,acc[3][1]);
            acc[3][2]=fmaf(xv.w,wv.z,acc[3][2]); acc[3][3]=fmaf(xv.w,wv.w,acc[3][3]);
        }
#pragma unroll
        for (int si=0; si<4; si++) {
            float4 r = make_float4(acc[si][0],acc[si][1],acc[si][2],acc[si][3]);
            *(float4*)&g_z[(size_t)(base+s0+si)*Hh + o0] = r;
            stS[0]+=r.x; stS[1]+=r.y; stS[2]+=r.z; stS[3]+=r.w;
            stQ[0]=fmaf(r.x,r.x,stQ[0]); stQ[1]=fmaf(r.y,r.y,stQ[1]);
            stQ[2]=fmaf(r.z,r.z,stQ[2]); stQ[3]=fmaf(r.w,r.w,stQ[3]);
        }
        __syncthreads();
    }
#pragma unroll
    for (int j=0;j<4;j++){ atomicAdd(&ss[o0+j], stS[j]); atomicAdd(&sq[o0+j], stQ[j]); }
    __syncthreads();
    if (tid < 64) {
        atomicAdd(&d_stats[slot_z*256 + tid],      ss[tid]);
        atomicAdd(&d_stats[slot_z*256 + 64 + tid], sq[tid]);
    }
}

// ------- attentive pool --------------------------------------------------------
#define POOL_PTS   4
#define POOL_ITERS 32
__global__ void pool_kernel(const float* __restrict__ sw2, const float* __restrict__ sb2,
                            const float* __restrict__ mw,
                            int slot_y, int slot_z, int slot_g) {
    __shared__ float mwT[Hh*Hh];            // [c][o]
    __shared__ float xt[POOL_PTS][Kk*Hh];   // post-BN/relu x
    __shared__ float sc[POOL_PTS][Kk];
    __shared__ float featS[POOL_PTS][Hh];
    __shared__ float myS[64], ryS[64], mzS[64], rzS[64], sw2S[64];
    __shared__ float ss[64], sq[64];
    int tid = threadIdx.x;                  // 256
    for (int t=tid; t<Hh*Hh; t+=256) { int oo=t>>6, cc=t&63; mwT[cc*Hh+oo]=mw[t]; }
    if (tid < 64) {
        myS[tid]=d_mr[slot_y*256+tid]; ryS[tid]=d_mr[slot_y*256+128+tid];
        mzS[tid]=d_mr[slot_z*256+tid]; rzS[tid]=d_mr[slot_z*256+128+tid];
        sw2S[tid]=sw2[tid]; ss[tid]=0.f; sq[tid]=0.f;
    }
    float sb = sb2[0];
    int pp = tid>>6, o = tid&63;
    int pq = tid>>6, kq = (tid>>2)&15, cg = tid&3;
    float gS = 0.f, gQ = 0.f;
    __syncthreads();
    for (int it=0; it<POOL_ITERS; it++) {
        int p0 = (blockIdx.x*POOL_ITERS + it)*POOL_PTS;
        const float4* xsrc = (const float4*)(g_x + (size_t)p0*Kk*Hh);
        for (int t=tid; t<POOL_PTS*Kk*Hh/4; t+=256) {
            float4 v = xsrc[t];
            int pt = t>>8, r = t&255;
            int c = (r&15)*4;
            v.x = fmaxf((v.x-myS[c  ])*ryS[c  ], 0.f);
            v.y = fmaxf((v.y-myS[c+1])*ryS[c+1], 0.f);
            v.z = fmaxf((v.z-myS[c+2])*ryS[c+2], 0.f);
            v.w = fmaxf((v.w-myS[c+3])*ryS[c+3], 0.f);
            ((float4*)xt[pt])[r] = v;
        }
        // scores straight from global z
        {
            const float4* zp = (const float4*)(g_z + (size_t)(p0+pq)*Kk*Hh + kq*Hh + cg*16);
            float sacc = 0.f;
#pragma unroll
            for (int q=0; q<4; q++) {
                float4 v = zp[q];
                int c = cg*16 + q*4;
                sacc += fmaxf((v.x-mzS[c  ])*rzS[c  ],0.f)*sw2S[c  ];
                sacc += fmaxf((v.y-mzS[c+1])*rzS[c+1],0.f)*sw2S[c+1];
                sacc += fmaxf((v.z-mzS[c+2])*rzS[c+2],0.f)*sw2S[c+2];
                sacc += fmaxf((v.w-mzS[c+3])*rzS[c+3],0.f)*sw2S[c+3];
            }
            sacc += __shfl_xor_sync(0xffffffffu, sacc, 1, 4);
            sacc += __shfl_xor_sync(0xffffffffu, sacc, 2, 4);
            if (cg == 0) sc[pq][kq] = sacc + sb;
        }
        __syncthreads();
        // softmax over k + weighted pool per (point, channel)
        float mx = sc[pp][0];
#pragma unroll
        for (int k=1;k<16;k++) mx = fmaxf(mx, sc[pp][k]);
        float pk[16], den=0.f;
#pragma unroll
        for (int k=0;k<16;k++){ pk[k]=__expf(sc[pp][k]-mx); den+=pk[k]; }
        float inv = 1.f/den;
        float feat = 0.f;
#pragma unroll
        for (int k=0;k<16;k++) feat = fmaf(xt[pp][k*Hh+o], pk[k], feat);
        feat *= inv;
        featS[pp][o] = feat;
        __syncthreads();
        float gv = 0.f;
#pragma unroll
        for (int c=0;c<Hh;c++) gv = fmaf(featS[pp][c], mwT[c*Hh+o], gv);
        g_g[(size_t)(p0+pp)*Hh + o] = gv;
        gS += gv; gQ = fmaf(gv, gv, gQ);
        __syncthreads();
    }
    atomicAdd(&ss[o], gS); atomicAdd(&sq[o], gQ);
    __syncthreads();
    if (tid < 64) {
        atomicAdd(&d_stats[slot_g*256 + tid],      ss[tid]);
        atomicAdd(&d_stats[slot_g*256 + 64 + tid], sq[tid]);
    }
}

// ------- f = relu(bn(g)) -> agg ------------------------------------------------
__global__ void apply_f_kernel(int slot_g, int broff) {
    int t = blockIdx.x*256 + threadIdx.x;    // P_TOT*16 float4s
    int p = t >> 4, q = t & 15, c = q*4;
    float4 v = ((const float4*)(g_g + (size_t)p*Hh))[q];
    const float* m = &d_mr[slot_g*256];
    const float* r = &d_mr[slot_g*256 + 128];
    v.x = fmaxf((v.x-m[c  ])*r[c  ], 0.f);
    v.y = fmaxf((v.y-m[c+1])*r[c+1], 0.f);
    v.z = fmaxf((v.z-m[c+2])*r[c+2], 0.f);
    v.w = fmaxf((v.w-m[c+3])*r[c+3], 0.f);
    *(float4*)(g_agg + (size_t)p*OUTC + broff + c) = v;
}

// ------- DRB matmul: register-tiled K=128 -------------------------------------
#define DRB_TILES 2
__global__ void drb_mm_kernel(const float* __restrict__ w, int mode) {
    extern __shared__ float dsh[];
    float* w2 = dsh;                 // [k][o] 128x128
    float* xT = dsh + OUTC*OUTC;     // [k][68]
    __shared__ float mS[OUTC], rS[OUTC], ss[OUTC], sq[OUTC];
    const float* src = (mode==0) ? g_agg : g_h1;
    float*       dst = (mode==0) ? g_h1  : g_h2;
    int slot_in  = (mode==0) ? -1 : 6;
    int slot_out = (mode==0) ?  6 : 7;
    int tid = threadIdx.x;           // 256
    int ts = tid & 15, to = tid >> 4;
    int s0 = ts*4, o0 = to*8;
    for (int t=tid; t<OUTC*OUTC; t+=256) { int oo=t>>7, kk=t&127; w2[kk*OUTC+oo]=w[t]; }
    if (tid < 128) {
        ss[tid]=0.f; sq[tid]=0.f;
        if (slot_in >= 0) { mS[tid]=d_mr[slot_in*256+tid]; rS[tid]=d_mr[slot_in*256+128+tid]; }
        else              { mS[tid]=0.f; rS[tid]=1.f; }
    }
    bool dobn = (slot_in >= 0);
    float stS[8]={0,0,0,0,0,0,0,0}, stQ[8]={0,0,0,0,0,0,0,0};
    __syncthreads();
    for (int tile=0; tile<DRB_TILES; tile++) {
        int base = (blockIdx.x*DRB_TILES + tile)*64;
        for (int t=tid; t<64*32; t+=256) {
            int s = t>>5, q = t&31;
            float4 v = ((const float4*)(src + (size_t)(base+s)*OUTC))[q];
            int c = q*4;
            if (dobn) {
                v.x = fmaxf((v.x-mS[c  ])*rS[c  ], 0.f);
                v.y = fmaxf((v.y-mS[c+1])*rS[c+1], 0.f);
                v.z = fmaxf((v.z-mS[c+2])*rS[c+2], 0.f);
                v.w = fmaxf((v.w-mS[c+3])*rS[c+3], 0.f);
            }
            xT[(c  )*68+s]=v.x; xT[(c+1)*68+s]=v.y; xT[(c+2)*68+s]=v.z; xT[(c+3)*68+s]=v.w;
        }
        __syncthreads();
        float acc[4][8] = {};
#pragma unroll 8
        for (int k=0;k<OUTC;k++) {
            float4 xv = *(const float4*)&xT[k*68 + s0];
            float4 w0 = *(const float4*)&w2[k*OUTC + o0];
            float4 w1 = *(const float4*)&w2[k*OUTC + o0 + 4];
            float xs[4] = {xv.x, xv.y, xv.z, xv.w};
#pragma unroll
            for (int si=0; si<4; si++) {
                acc[si][0]=fmaf(xs[si],w0.x,acc[si][0]); acc[si][1]=fmaf(xs[si],w0.y,acc[si][1]);
                acc[si][2]=fmaf(xs[si],w0.z,acc[si][2]); acc[si][3]=fmaf(xs[si],w0.w,acc[si][3]);
                acc[si][4]=fmaf(xs[si],w1.x,acc[si][4]); acc[si][5]=fmaf(xs[si],w1.y,acc[si][5]);
                acc[si][6]=fmaf(xs[si],w1.z,acc[si][6]); acc[si][7]=fmaf(xs[si],w1.w,acc[si][7]);
            }
        }
#pragma unroll
        for (int si=0; si<4; si++) {
            float4 r0 = make_float4(acc[si][0],acc[si][1],acc[si][2],acc[si][3]);
            float4 r1 = make_float4(acc[si][4],acc[si][5],acc[si][6],acc[si][7]);
            float* drow = dst + (size_t)(base+s0+si)*OUTC + o0;
            *(float4*)drow = r0; *(float4*)(drow+4) = r1;
#pragma unroll
            for (int j=0;j<4;j++){ stS[j]+=(&r0.x)[j]; stQ[j]=fmaf((&r0.x)[j],(&r0.x)[j],stQ[j]); }
#pragma unroll
            for (int j=0;j<4;j++){ stS[4+j]+=(&r1.x)[j]; stQ[4+j]=fmaf((&r1.x)[j],(&r1.x)[j],stQ[4+j]); }
        }
        __syncthreads();
    }
#pragma unroll
    for (int j=0;j<8;j++){ atomicAdd(&ss[o0+j], stS[j]); atomicAdd(&sq[o0+j], stQ[j]); }
    __syncthreads();
    if (tid < 128) {
        atomicAdd(&d_stats[slot_out*256 + tid],       ss[tid]);
        atomicAdd(&d_stats[slot_out*256 + 128 + tid], sq[tid]);
    }
}

// ------- out = relu(bn(h2) + agg) ---------------------------------------------
__global__ void final_kernel(float* __restrict__ out) {
    int t = blockIdx.x*256 + threadIdx.x;    // P_TOT*32 float4s
    int q = t & 31, c = q*4;
    float4 h = ((const float4*)g_h2)[t];
    float4 a = ((const float4*)g_agg)[t];
    const float* m = &d_mr[7*256];
    const float* r = &d_mr[7*256 + 128];
    float4 o;
    o.x = fmaxf((h.x-m[c  ])*r[c  ] + a.x, 0.f);
    o.y = fmaxf((h.y-m[c+1])*r[c+1] + a.y, 0.f);
    o.z = fmaxf((h.z-m[c+2])*r[c+2] + a.z, 0.f);
    o.w = fmaxf((h.w-m[c+3])*r[c+3] + a.w, 0.f);
    ((float4*)out)[t] = o;
}

// ------------------------------ launch ----------------------------------------
extern "C" void kernel_launch(void* const* d_in, const int* in_sizes, int n_in,
                              void* d_out, int out_size) {
    const float* xyz     = (const float*)d_in[0];
    const float* feat    = (const float*)d_in[1];
    const float* w_lse1  = (const float*)d_in[2];
    const float* w_lse2  = (const float*)d_in[3];
    const float* ap1_sw1 = (const float*)d_in[4];
    const float* ap1_sw2 = (const float*)d_in[5];
    const float* ap1_sb2 = (const float*)d_in[6];
    const float* ap1_mw  = (const float*)d_in[7];
    const float* ap2_sw1 = (const float*)d_in[8];
    const float* ap2_sw2 = (const float*)d_in[9];
    const float* ap2_sb2 = (const float*)d_in[10];
    const float* ap2_mw  = (const float*)d_in[11];
    const float* drb_w1  = (const float*)d_in[12];
    const float* drb_w2  = (const float*)d_in[13];
    float* out = (float*)d_out;

    size_t dsm = (size_t)(OUTC*OUTC + OUTC*68) * sizeof(float);   // ~98 KB
    cudaFuncSetAttribute(drb_mm_kernel, cudaFuncAttributeMaxDynamicSharedMemorySize, (int)dsm);

    const float inv_S = 1.f/(float)S_TOT;
    const float inv_P = 1.f/(float)P_TOT;

    zero_stats_kernel<<<8,256>>>();
    knn_kernel<<<dim3(Nn/KNN_T, Bz), KNN_T>>>(xyz);

    // branch 1
    lse_kernel<<<512,256>>>(xyz, feat, w_lse1, 0);
    finalize_kernel<<<1,128>>>(0, inv_S, 64);
    xz_kernel<<<512,256>>>(ap1_sw1, 0, 1);
    finalize_kernel<<<1,128>>>(1, inv_S, 64);
    pool_kernel<<<256,256>>>(ap1_sw2, ap1_sb2, ap1_mw, 0, 1, 2);
    finalize_kernel<<<1,128>>>(2, inv_P, 64);
    apply_f_kernel<<<P_TOT*16/256,256>>>(2, 0);

    // branch 2
    lse_kernel<<<512,256>>>(xyz, feat, w_lse2, 3);
    finalize_kernel<<<1,128>>>(3, inv_S, 64);
    xz_kernel<<<512,256>>>(ap2_sw1, 3, 4);
    finalize_kernel<<<1,128>>>(4, inv_S, 64);
    pool_kernel<<<256,256>>>(ap2_sw2, ap2_sb2, ap2_mw, 3, 4, 5);
    finalize_kernel<<<1,128>>>(5, inv_P, 64);
    apply_f_kernel<<<P_TOT*16/256,256>>>(5, 64);

    // dilated residual block
    drb_mm_kernel<<<256,256,dsm>>>(drb_w1, 0);
    finalize_kernel<<<1,128>>>(6, inv_P, 128);
    drb_mm_kernel<<<256,256,dsm>>>(drb_w2, 1);
    finalize_kernel<<<1,128>>>(7, inv_P, 128);
    final_kernel<<<P_TOT*32/256,256>>>(out);
}

// round 3
// speedup vs baseline: 1.9745x; 1.3220x over previous
#include <cuda_runtime.h>
#include <math.h>

#define Bz   4
#define Nn   8192
#define Cc   32
#define Kk   16
#define Hh   64
#define OUTC 128
#define CE   36
#define S_TOT (Bz*Nn*Kk)        // 524288
#define P_TOT (Bz*Nn)           // 32768

// ---------------- scratch -----------------------------------------------------
__device__ float g_x1 [S_TOT*Hh];   // branch1 lse pre-BN y
__device__ float g_x2 [S_TOT*Hh];   // branch2 lse pre-BN y
__device__ float g_z1 [S_TOT*Hh];
__device__ float g_z2 [S_TOT*Hh];
__device__ float g_g1 [P_TOT*Hh];
__device__ float g_g2 [P_TOT*Hh];
__device__ float g_agg[P_TOT*OUTC];
__device__ float g_h1 [P_TOT*OUTC];
__device__ float g_h2 [P_TOT*OUTC];
__device__ int   g_idx[S_TOT];
__device__ float d_stats[8*256];
__device__ float d_mr  [8*256];     // mean at [0..), rstd at [128..)

__device__ __forceinline__ unsigned tf32r(float f) {
    unsigned r; asm("cvt.rna.tf32.f32 %0, %1;" : "=r"(r) : "f"(f)); return r;
}
#define MMA_TF32(d, a, b) asm volatile( \
    "mma.sync.aligned.m16n8k8.row.col.f32.tf32.tf32.f32 " \
    "{%0,%1,%2,%3}, {%4,%5,%6,%7}, {%8,%9}, {%0,%1,%2,%3};" \
    : "+f"(d[0]),"+f"(d[1]),"+f"(d[2]),"+f"(d[3]) \
    : "r"(a[0]),"r"(a[1]),"r"(a[2]),"r"(a[3]), "r"(b[0]),"r"(b[1]))

__global__ void zero_stats_kernel() {
    int t = blockIdx.x*256 + threadIdx.x;
    if (t < 8*256) d_stats[t] = 0.f;
}

// ---------------- KNN ---------------------------------------------------------
#define KNN_T    128
#define KNN_TILE 512
__global__ void knn_kernel(const float* __restrict__ xyz) {
    int b = blockIdx.y;
    int n = blockIdx.x*KNN_T + threadIdx.x;
    const float* xb = xyz + b*Nn*3;
    float qx = xb[n*3+0], qy = xb[n*3+1], qz = xb[n*3+2];
    float m2x = -2.f*qx, m2y = -2.f*qy, m2z = -2.f*qz;
    float bd[16]; int bi[16];
#pragma unroll
    for (int t=0;t<16;t++){ bd[t]=3.4e38f; bi[t]=0; }
    __shared__ float4 sp[KNN_TILE];
    for (int tile=0; tile<Nn; tile+=KNN_TILE) {
        __syncthreads();
        for (int t=threadIdx.x; t<KNN_TILE; t+=KNN_T) {
            int j = tile + t;
            float x = xb[j*3+0], y = xb[j*3+1], z = xb[j*3+2];
            float w = x*x; w = fmaf(y,y,w); w = fmaf(z,z,w);
            sp[t] = make_float4(x, y, z, w);
        }
        __syncthreads();
#pragma unroll 8
        for (int jj=0; jj<KNN_TILE; jj++) {
            float4 c = sp[jj];
            float d = fmaf(c.x, m2x, fmaf(c.y, m2y, fmaf(c.z, m2z, c.w)));
            if (d < bd[15]) {
                bd[15]=d; bi[15]=tile+jj;
#pragma unroll
                for (int t=15;t>0;t--) {
                    if (bd[t] < bd[t-1]) {
                        float td=bd[t]; bd[t]=bd[t-1]; bd[t-1]=td;
                        int   ti=bi[t]; bi[t]=bi[t-1]; bi[t-1]=ti;
                    }
                }
            }
        }
    }
    int base = (b*Nn + n)*Kk;
#pragma unroll
    for (int t=0;t<16;t++) g_idx[base+t] = bi[t];
}

// ---------------- finalize BN stats -------------------------------------------
__global__ void finalize_kernel(int slot, float inv_cnt, int nch) {
    int o = threadIdx.x;
    if (o < nch) {
        float m = d_stats[slot*256 + o] * inv_cnt;
        float v = d_stats[slot*256 + nch + o] * inv_cnt - m*m;
        d_mr[slot*256 + o]       = m;
        d_mr[slot*256 + 128 + o] = rsqrtf(v + 1e-5f);
    }
}

// ---------------- LSE both branches: enc[40] @ [w1|w2] -> g_x1,g_x2 -----------
#define LSE_TILES 16
__global__ void lse_mma_kernel(const float* __restrict__ xyz, const float* __restrict__ feat,
                               const float* __restrict__ w1, const float* __restrict__ w2) {
    __shared__ unsigned encS[64*44];    // [s][kpad]
    __shared__ unsigned wS[128*44];     // [n][kpad]
    __shared__ float ssS[128], sqS[128];
    int tid = threadIdx.x;              // 256
    for (int i=tid; i<128*44; i+=256) wS[i] = 0u;
    for (int i=tid; i<64*44;  i+=256) encS[i] = 0u;
    if (tid < 128) { ssS[tid]=0.f; sqS[tid]=0.f; }
    __syncthreads();
    for (int i=tid; i<128*CE; i+=256) {
        int n = i/CE, k = i - n*CE;
        float v = (n < 64) ? w1[n*CE+k] : w2[(n-64)*CE+k];
        wS[n*44+k] = tf32r(v);
    }
    int w = tid>>5, lane = tid&31, g = lane>>2, t4 = lane&3;
    int wM = w&1, wN = w>>1;
    int sOffW = wM*32, nOffW = wN*32;
    int sl = tid>>2, gq = tid&3;
    float stS[8]={0,0,0,0,0,0,0,0}, stQ[8]={0,0,0,0,0,0,0,0};
    __syncthreads();
    for (int tile=0; tile<LSE_TILES; tile++) {
        int base = (blockIdx.x*LSE_TILES + tile)*64;
        {   // build enc tile (4 threads per sample)
            int s = base + sl;
            int b = s >> 17;
            int n = (s >> 4) & (Nn-1);
            int j = g_idx[s];
            const float4* fp = (const float4*)(feat + (size_t)(b*Nn + j)*Cc + gq*8);
            float4 v0 = fp[0], v1 = fp[1];
            unsigned* e = &encS[sl*44 + 4 + gq*8];
            e[0]=tf32r(v0.x); e[1]=tf32r(v0.y); e[2]=tf32r(v0.z); e[3]=tf32r(v0.w);
            e[4]=tf32r(v1.x); e[5]=tf32r(v1.y); e[6]=tf32r(v1.z); e[7]=tf32r(v1.w);
            if (gq == 0) {
                const float* pj = xyz + (size_t)(b*Nn + j)*3;
                const float* pn = xyz + (size_t)(b*Nn + n)*3;
                float dx=pj[0]-pn[0], dy=pj[1]-pn[1], dz=pj[2]-pn[2];
                float dd = dx*dx; dd=fmaf(dy,dy,dd); dd=fmaf(dz,dz,dd);
                encS[sl*44+0]=tf32r(dx); encS[sl*44+1]=tf32r(dy);
                encS[sl*44+2]=tf32r(dz); encS[sl*44+3]=tf32r(sqrtf(fmaxf(dd,1e-12f)));
            }
        }
        __syncthreads();
        float acc[2][4][4];
#pragma unroll
        for (int m=0;m<2;m++)
#pragma unroll
        for (int n=0;n<4;n++)
#pragma unroll
        for (int c=0;c<4;c++) acc[m][n][c]=0.f;
#pragma unroll
        for (int kk=0; kk<5; kk++) {
            int k0 = kk*8;
            unsigned a[2][4], b[4][2];
#pragma unroll
            for (int m=0;m<2;m++) {
                int r0 = (sOffW + m*16 + g)*44 + k0 + t4;
                a[m][0]=encS[r0]; a[m][1]=encS[r0+8*44];
                a[m][2]=encS[r0+4]; a[m][3]=encS[r0+8*44+4];
            }
#pragma unroll
            for (int n=0;n<4;n++) {
                int rb = (nOffW + n*8 + g)*44 + k0 + t4;
                b[n][0]=wS[rb]; b[n][1]=wS[rb+4];
            }
#pragma unroll
            for (int m=0;m<2;m++)
#pragma unroll
            for (int n=0;n<4;n++) MMA_TF32(acc[m][n], a[m], b[n]);
        }
#pragma unroll
        for (int m=0;m<2;m++)
#pragma unroll
        for (int n=0;n<4;n++) {
            int row = base + sOffW + m*16 + g;
            int col = nOffW + n*8 + 2*t4;
            float* dst = (col < 64) ? g_x1 : g_x2;
            int cc = col & 63;
            *(float2*)&dst[(size_t)row*Hh + cc]     = make_float2(acc[m][n][0], acc[m][n][1]);
            *(float2*)&dst[(size_t)(row+8)*Hh + cc] = make_float2(acc[m][n][2], acc[m][n][3]);
            stS[n*2  ] += acc[m][n][0] + acc[m][n][2];
            stS[n*2+1] += acc[m][n][1] + acc[m][n][3];
            stQ[n*2  ] = fmaf(acc[m][n][0],acc[m][n][0], fmaf(acc[m][n][2],acc[m][n][2], stQ[n*2  ]));
            stQ[n*2+1] = fmaf(acc[m][n][1],acc[m][n][1], fmaf(acc[m][n][3],acc[m][n][3], stQ[n*2+1]));
        }
        __syncthreads();
    }
#pragma unroll
    for (int n=0;n<4;n++)
#pragma unroll
    for (int p=0;p<2;p++) {
        int col = nOffW + n*8 + 2*t4 + p;
        atomicAdd(&ssS[col], stS[n*2+p]);
        atomicAdd(&sqS[col], stQ[n*2+p]);
    }
    __syncthreads();
    if (tid < 128) {
        int slot = (tid < 64) ? 0 : 3;
        int ch = tid & 63;
        atomicAdd(&d_stats[slot*256 + ch],      ssS[tid]);
        atomicAdd(&d_stats[slot*256 + 64 + ch], sqS[tid]);
    }
}

// ------- xz (tf32): z = relu(bn(y)) @ sw1^T (+stats) ---------------------------
#define XZ_TILES 8
__global__ void xz_mma_kernel(const float* __restrict__ src, float* __restrict__ dst,
                              const float* __restrict__ sw1, int slot_y, int slot_z) {
    extern __shared__ unsigned sh[];
    unsigned* xT = sh;              // [128][68]
    unsigned* wS = sh + 128*68;     // [64][68]
    __shared__ float mS[64], rS[64], ssS[64], sqS[64];
    int tid = threadIdx.x;          // 256
    for (int i=tid; i<Hh*Hh; i+=256) {
        int n = i>>6, k = i&63;
        wS[n*68+k] = tf32r(sw1[i]);
    }
    if (tid < 64) {
        mS[tid]=d_mr[slot_y*256+tid]; rS[tid]=d_mr[slot_y*256+128+tid];
        ssS[tid]=0.f; sqS[tid]=0.f;
    }
    int w = tid>>5, lane = tid&31, g = lane>>2, t4 = lane&3;
    int wM = w&3, wN = w>>2;
    int sOffW = wM*32, nOffW = wN*32;
    float stS[8]={0,0,0,0,0,0,0,0}, stQ[8]={0,0,0,0,0,0,0,0};
    __syncthreads();
    for (int tile=0; tile<XZ_TILES; tile++) {
        int base = (blockIdx.x*XZ_TILES + tile)*128;
        for (int i=tid; i<128*16; i+=256) {
            int s = i>>4, q = i&15, c = q*4;
            float4 v = ((const float4*)(src + (size_t)(base+s)*Hh))[q];
            uint4 u;
            u.x = tf32r(fmaxf((v.x-mS[c  ])*rS[c  ], 0.f));
            u.y = tf32r(fmaxf((v.y-mS[c+1])*rS[c+1], 0.f));
            u.z = tf32r(fmaxf((v.z-mS[c+2])*rS[c+2], 0.f));
            u.w = tf32r(fmaxf((v.w-mS[c+3])*rS[c+3], 0.f));
            *(uint4*)&xT[s*68 + c] = u;
        }
        __syncthreads();
        float acc[2][4][4];
#pragma unroll
        for (int m=0;m<2;m++)
#pragma unroll
        for (int n=0;n<4;n++)
#pragma unroll
        for (int c=0;c<4;c++) acc[m][n][c]=0.f;
#pragma unroll
        for (int kk=0; kk<8; kk++) {
            int k0 = kk*8;
            unsigned a[2][4], b[4][2];
#pragma unroll
            for (int m=0;m<2;m++) {
                int r0 = (sOffW + m*16 + g)*68 + k0 + t4;
                a[m][0]=xT[r0]; a[m][1]=xT[r0+8*68];
                a[m][2]=xT[r0+4]; a[m][3]=xT[r0+8*68+4];
            }
#pragma unroll
            for (int n=0;n<4;n++) {
                int rb = (nOffW + n*8 + g)*68 + k0 + t4;
                b[n][0]=wS[rb]; b[n][1]=wS[rb+4];
            }
#pragma unroll
            for (int m=0;m<2;m++)
#pragma unroll
            for (int n=0;n<4;n++) MMA_TF32(acc[m][n], a[m], b[n]);
        }
#pragma unroll
        for (int m=0;m<2;m++)
#pragma unroll
        for (int n=0;n<4;n++) {
            int row = base + sOffW + m*16 + g;
            int col = nOffW + n*8 + 2*t4;
            *(float2*)&dst[(size_t)row*Hh + col]     = make_float2(acc[m][n][0], acc[m][n][1]);
            *(float2*)&dst[(size_t)(row+8)*Hh + col] = make_float2(acc[m][n][2], acc[m][n][3]);
            stS[n*2  ] += acc[m][n][0] + acc[m][n][2];
            stS[n*2+1] += acc[m][n][1] + acc[m][n][3];
            stQ[n*2  ] = fmaf(acc[m][n][0],acc[m][n][0], fmaf(acc[m][n][2],acc[m][n][2], stQ[n*2  ]));
            stQ[n*2+1] = fmaf(acc[m][n][1],acc[m][n][1], fmaf(acc[m][n][3],acc[m][n][3], stQ[n*2+1]));
        }
        __syncthreads();
    }
#pragma unroll
    for (int n=0;n<4;n++)
#pragma unroll
    for (int p=0;p<2;p++) {
        int col = nOffW + n*8 + 2*t4 + p;
        atomicAdd(&ssS[col], stS[n*2+p]);
        atomicAdd(&sqS[col], stQ[n*2+p]);
    }
    __syncthreads();
    if (tid < 64) {
        atomicAdd(&d_stats[slot_z*256 + tid],      ssS[tid]);
        atomicAdd(&d_stats[slot_z*256 + 64 + tid], sqS[tid]);
    }
}

// ------- attentive pool (fp32, per branch) -------------------------------------
#define POOL_PTS   4
#define POOL_ITERS 32
__global__ void pool_kernel(const float* __restrict__ gx, const float* __restrict__ gz,
                            float* __restrict__ gg,
                            const float* __restrict__ sw2, const float* __restrict__ sb2,
                            const float* __restrict__ mw,
                            int slot_y, int slot_z, int slot_g) {
    __shared__ float mwT[Hh*Hh];
    __shared__ float xt[POOL_PTS][Kk*Hh];
    __shared__ float sc[POOL_PTS][Kk];
    __shared__ float featS[POOL_PTS][Hh];
    __shared__ float myS[64], ryS[64], mzS[64], rzS[64], sw2S[64];
    __shared__ float ss[64], sq[64];
    int tid = threadIdx.x;          // 256
    for (int t=tid; t<Hh*Hh; t+=256) { int oo=t>>6, cc=t&63; mwT[cc*Hh+oo]=mw[t]; }
    if (tid < 64) {
        myS[tid]=d_mr[slot_y*256+tid]; ryS[tid]=d_mr[slot_y*256+128+tid];
        mzS[tid]=d_mr[slot_z*256+tid]; rzS[tid]=d_mr[slot_z*256+128+tid];
        sw2S[tid]=sw2[tid]; ss[tid]=0.f; sq[tid]=0.f;
    }
    float sb = sb2[0];
    int pp = tid>>6, o = tid&63;
    int pq = tid>>6, kq = (tid>>2)&15, cg = tid&3;
    float gS = 0.f, gQ = 0.f;
    __syncthreads();
    for (int it=0; it<POOL_ITERS; it++) {
        int p0 = (blockIdx.x*POOL_ITERS + it)*POOL_PTS;
        const float4* xsrc = (const float4*)(gx + (size_t)p0*Kk*Hh);
        for (int t=tid; t<POOL_PTS*Kk*Hh/4; t+=256) {
            float4 v = xsrc[t];
            int pt = t>>8, r = t&255;
            int c = (r&15)*4;
            v.x = fmaxf((v.x-myS[c  ])*ryS[c  ], 0.f);
            v.y = fmaxf((v.y-myS[c+1])*ryS[c+1], 0.f);
            v.z = fmaxf((v.z-myS[c+2])*ryS[c+2], 0.f);
            v.w = fmaxf((v.w-myS[c+3])*ryS[c+3], 0.f);
            ((float4*)xt[pt])[r] = v;
        }
        {
            const float4* zp = (const float4*)(gz + (size_t)(p0+pq)*Kk*Hh + kq*Hh + cg*16);
            float sacc = 0.f;
#pragma unroll
            for (int q=0; q<4; q++) {
                float4 v = zp[q];
                int c = cg*16 + q*4;
                sacc += fmaxf((v.x-mzS[c  ])*rzS[c  ],0.f)*sw2S[c  ];
                sacc += fmaxf((v.y-mzS[c+1])*rzS[c+1],0.f)*sw2S[c+1];
                sacc += fmaxf((v.z-mzS[c+2])*rzS[c+2],0.f)*sw2S[c+2];
                sacc += fmaxf((v.w-mzS[c+3])*rzS[c+3],0.f)*sw2S[c+3];
            }
            sacc += __shfl_xor_sync(0xffffffffu, sacc, 1, 4);
            sacc += __shfl_xor_sync(0xffffffffu, sacc, 2, 4);
            if (cg == 0) sc[pq][kq] = sacc + sb;
        }
        __syncthreads();
        float mx = sc[pp][0];
#pragma unroll
        for (int k=1;k<16;k++) mx = fmaxf(mx, sc[pp][k]);
        float pk[16], den=0.f;
#pragma unroll
        for (int k=0;k<16;k++){ pk[k]=__expf(sc[pp][k]-mx); den+=pk[k]; }
        float inv = 1.f/den;
        float feat = 0.f;
#pragma unroll
        for (int k=0;k<16;k++) feat = fmaf(xt[pp][k*Hh+o], pk[k], feat);
        feat *= inv;
        featS[pp][o] = feat;
        __syncthreads();
        float gv = 0.f;
#pragma unroll
        for (int c=0;c<Hh;c++) gv = fmaf(featS[pp][c], mwT[c*Hh+o], gv);
        gg[(size_t)(p0+pp)*Hh + o] = gv;
        gS += gv; gQ = fmaf(gv, gv, gQ);
        __syncthreads();
    }
    atomicAdd(&ss[o], gS); atomicAdd(&sq[o], gQ);
    __syncthreads();
    if (tid < 64) {
        atomicAdd(&d_stats[slot_g*256 + tid],      ss[tid]);
        atomicAdd(&d_stats[slot_g*256 + 64 + tid], sq[tid]);
    }
}

// ------- f = relu(bn(g)) -> agg ------------------------------------------------
__global__ void apply_f_kernel(const float* __restrict__ gg, int slot_g, int broff) {
    int t = blockIdx.x*256 + threadIdx.x;
    int p = t >> 4, q = t & 15, c = q*4;
    float4 v = ((const float4*)(gg + (size_t)p*Hh))[q];
    const float* m = &d_mr[slot_g*256];
    const float* r = &d_mr[slot_g*256 + 128];
    v.x = fmaxf((v.x-m[c  ])*r[c  ], 0.f);
    v.y = fmaxf((v.y-m[c+1])*r[c+1], 0.f);
    v.z = fmaxf((v.z-m[c+2])*r[c+2], 0.f);
    v.w = fmaxf((v.w-m[c+3])*r[c+3], 0.f);
    *(float4*)(g_agg + (size_t)p*OUTC + broff + c) = v;
}

// ------- DRB matmul (tf32): out = (opt relu(bn(src))) @ w^T (+stats) ----------
__global__ void drb_mma_kernel(const float* __restrict__ src, float* __restrict__ dst,
                               const float* __restrict__ wmat, int slot_in, int slot_out) {
    extern __shared__ unsigned sh[];
    unsigned* xT = sh;               // [128][132]
    unsigned* wS = sh + 128*132;     // [128][132]
    __shared__ float mS[OUTC], rS[OUTC], ssS[OUTC], sqS[OUTC];
    int tid = threadIdx.x;           // 512
    for (int i=tid; i<OUTC*OUTC; i+=512) {
        int n = i>>7, k = i&127;
        wS[n*132+k] = tf32r(wmat[i]);
    }
    if (tid < 128) {
        ssS[tid]=0.f; sqS[tid]=0.f;
        if (slot_in >= 0) { mS[tid]=d_mr[slot_in*256+tid]; rS[tid]=d_mr[slot_in*256+128+tid]; }
        else              { mS[tid]=0.f; rS[tid]=1.f; }
    }
    bool dobn = (slot_in >= 0);
    int w = tid>>5, lane = tid&31, g = lane>>2, t4 = lane&3;
    int wM = w&3, wN = w>>2;
    int sOffW = wM*32, nOffW = wN*32;
    int base = blockIdx.x*128;
    __syncthreads();
    for (int i=tid; i<128*32; i+=512) {
        int s = i>>5, q = i&31, c = q*4;
        float4 v = ((const float4*)(src + (size_t)(base+s)*OUTC))[q];
        if (dobn) {
            v.x = fmaxf((v.x-mS[c  ])*rS[c  ], 0.f);
            v.y = fmaxf((v.y-mS[c+1])*rS[c+1], 0.f);
            v.z = fmaxf((v.z-mS[c+2])*rS[c+2], 0.f);
            v.w = fmaxf((v.w-mS[c+3])*rS[c+3], 0.f);
        }
        uint4 u; u.x=tf32r(v.x); u.y=tf32r(v.y); u.z=tf32r(v.z); u.w=tf32r(v.w);
        *(uint4*)&xT[s*132 + c] = u;
    }
    __syncthreads();
    float acc[2][4][4];
#pragma unroll
    for (int m=0;m<2;m++)
#pragma unroll
    for (int n=0;n<4;n++)
#pragma unroll
    for (int c=0;c<4;c++) acc[m][n][c]=0.f;
#pragma unroll
    for (int kk=0; kk<16; kk++) {
        int k0 = kk*8;
        unsigned a[2][4], b[4][2];
#pragma unroll
        for (int m=0;m<2;m++) {
            int r0 = (sOffW + m*16 + g)*132 + k0 + t4;
            a[m][0]=xT[r0]; a[m][1]=xT[r0+8*132];
            a[m][2]=xT[r0+4]; a[m][3]=xT[r0+8*132+4];
        }
#pragma unroll
        for (int n=0;n<4;n++) {
            int rb = (nOffW + n*8 + g)*132 + k0 + t4;
            b[n][0]=wS[rb]; b[n][1]=wS[rb+4];
        }
#pragma unroll
        for (int m=0;m<2;m++)
#pragma unroll
        for (int n=0;n<4;n++) MMA_TF32(acc[m][n], a[m], b[n]);
    }
    float stS[8]={0,0,0,0,0,0,0,0}, stQ[8]={0,0,0,0,0,0,0,0};
#pragma unroll
    for (int m=0;m<2;m++)
#pragma unroll
    for (int n=0;n<4;n++) {
        int row = base + sOffW + m*16 + g;
        int col = nOffW + n*8 + 2*t4;
        *(float2*)&dst[(size_t)row*OUTC + col]     = make_float2(acc[m][n][0], acc[m][n][1]);
        *(float2*)&dst[(size_t)(row+8)*OUTC + col] = make_float2(acc[m][n][2], acc[m][n][3]);
        stS[n*2  ] += acc[m][n][0] + acc[m][n][2];
        stS[n*2+1] += acc[m][n][1] + acc[m][n][3];
        stQ[n*2  ] = fmaf(acc[m][n][0],acc[m][n][0], fmaf(acc[m][n][2],acc[m][n][2], stQ[n*2  ]));
        stQ[n*2+1] = fmaf(acc[m][n][1],acc[m][n][1], fmaf(acc[m][n][3],acc[m][n][3], stQ[n*2+1]));
    }
#pragma unroll
    for (int n=0;n<4;n++)
#pragma unroll
    for (int p=0;p<2;p++) {
        int col = nOffW + n*8 + 2*t4 + p;
        atomicAdd(&ssS[col], stS[n*2+p]);
        atomicAdd(&sqS[col], stQ[n*2+p]);
    }
    __syncthreads();
    if (tid < 128) {
        atomicAdd(&d_stats[slot_out*256 + tid],       ssS[tid]);
        atomicAdd(&d_stats[slot_out*256 + 128 + tid], sqS[tid]);
    }
}

// ------- out = relu(bn(h2) + agg) ---------------------------------------------
__global__ void final_kernel(float* __restrict__ out) {
    int t = blockIdx.x*256 + threadIdx.x;
    int q = t & 31, c = q*4;
    float4 h = ((const float4*)g_h2)[t];
    float4 a = ((const float4*)g_agg)[t];
    const float* m = &d_mr[7*256];
    const float* r = &d_mr[7*256 + 128];
    float4 o;
    o.x = fmaxf((h.x-m[c  ])*r[c  ] + a.x, 0.f);
    o.y = fmaxf((h.y-m[c+1])*r[c+1] + a.y, 0.f);
    o.z = fmaxf((h.z-m[c+2])*r[c+2] + a.z, 0.f);
    o.w = fmaxf((h.w-m[c+3])*r[c+3] + a.w, 0.f);
    ((float4*)out)[t] = o;
}

// ------------------------------ launch ----------------------------------------
extern "C" void kernel_launch(void* const* d_in, const int* in_sizes, int n_in,
                              void* d_out, int out_size) {
    const float* xyz     = (const float*)d_in[0];
    const float* feat    = (const float*)d_in[1];
    const float* w_lse1  = (const float*)d_in[2];
    const float* w_lse2  = (const float*)d_in[3];
    const float* ap1_sw1 = (const float*)d_in[4];
    const float* ap1_sw2 = (const float*)d_in[5];
    const float* ap1_sb2 = (const float*)d_in[6];
    const float* ap1_mw  = (const float*)d_in[7];
    const float* ap2_sw1 = (const float*)d_in[8];
    const float* ap2_sw2 = (const float*)d_in[9];
    const float* ap2_sb2 = (const float*)d_in[10];
    const float* ap2_mw  = (const float*)d_in[11];
    const float* drb_w1  = (const float*)d_in[12];
    const float* drb_w2  = (const float*)d_in[13];
    float* out = (float*)d_out;

    size_t xz_smem  = (size_t)(128*68 + 64*68) * 4;      // ~52 KB
    size_t drb_smem = (size_t)(128*132 + 128*132) * 4;   // ~135 KB
    cudaFuncSetAttribute(xz_mma_kernel,  cudaFuncAttributeMaxDynamicSharedMemorySize, (int)xz_smem);
    cudaFuncSetAttribute(drb_mma_kernel, cudaFuncAttributeMaxDynamicSharedMemorySize, (int)drb_smem);

    const float inv_S = 1.f/(float)S_TOT;
    const float inv_P = 1.f/(float)P_TOT;

    // get raw pointers to device globals (host-side address-of works via symbol)
    float *px1, *px2, *pz1, *pz2, *pg1, *pg2, *pagg, *ph1, *ph2;
    cudaGetSymbolAddress((void**)&px1, g_x1);
    cudaGetSymbolAddress((void**)&px2, g_x2);
    cudaGetSymbolAddress((void**)&pz1, g_z1);
    cudaGetSymbolAddress((void**)&pz2, g_z2);
    cudaGetSymbolAddress((void**)&pg1, g_g1);
    cudaGetSymbolAddress((void**)&pg2, g_g2);
    cudaGetSymbolAddress((void**)&pagg, g_agg);
    cudaGetSymbolAddress((void**)&ph1, g_h1);
    cudaGetSymbolAddress((void**)&ph2, g_h2);

    zero_stats_kernel<<<8,256>>>();                                     // 0
    knn_kernel<<<dim3(Nn/KNN_T, Bz), KNN_T>>>(xyz);                     // 1
    lse_mma_kernel<<<512,256>>>(xyz, feat, w_lse1, w_lse2);             // 2
    finalize_kernel<<<1,128>>>(0, inv_S, 64);                           // 3
    finalize_kernel<<<1,128>>>(3, inv_S, 64);                           // 4
    xz_mma_kernel<<<512,256,xz_smem>>>(px1, pz1, ap1_sw1, 0, 1);        // 5  <- ncu
    finalize_kernel<<<1,128>>>(1, inv_S, 64);                           // 6
    xz_mma_kernel<<<512,256,xz_smem>>>(px2, pz2, ap2_sw1, 3, 4);        // 7
    finalize_kernel<<<1,128>>>(4, inv_S, 64);                           // 8
    pool_kernel<<<256,256>>>(px1, pz1, pg1, ap1_sw2, ap1_sb2, ap1_mw, 0, 1, 2);  // 9
    finalize_kernel<<<1,128>>>(2, inv_P, 64);                           // 10
    pool_kernel<<<256,256>>>(px2, pz2, pg2, ap2_sw2, ap2_sb2, ap2_mw, 3, 4, 5);  // 11
    finalize_kernel<<<1,128>>>(5, inv_P, 64);                           // 12
    apply_f_kernel<<<P_TOT*16/256,256>>>(pg1, 2, 0);                    // 13
    apply_f_kernel<<<P_TOT*16/256,256>>>(pg2, 5, 64);                   // 14
    drb_mma_kernel<<<256,512,drb_smem>>>(pagg, ph1, drb_w1, -1, 6);     // 15
    finalize_kernel<<<1,128>>>(6, inv_P, 128);                          // 16
    drb_mma_kernel<<<256,512,drb_smem>>>(ph1, ph2, drb_w2, 6, 7);       // 17
    finalize_kernel<<<1,128>>>(7, inv_P, 128);                          // 18
    final_kernel<<<P_TOT*32/256,256>>>(out);                            // 19
}

// round 4
// speedup vs baseline: 2.2445x; 1.1367x over previous
#include <cuda_runtime.h>
#include <cuda_fp16.h>
#include <math.h>

#define Bz   4
#define Nn   8192
#define Cc   32
#define Kk   16
#define Hh   64
#define OUTC 128
#define CE   36
#define S_TOT (Bz*Nn*Kk)        // 524288
#define P_TOT (Bz*Nn)           // 32768
#define INV_S (1.f/524288.f)
#define INV_P (1.f/32768.f)

// ---------------- scratch -----------------------------------------------------
__device__ __half g_y1 [S_TOT*Hh];  // branch1 lse pre-BN y (fp16)
__device__ __half g_y2 [S_TOT*Hh];
__device__ __half g_z1 [S_TOT*Hh];  // pre-BN score-MLP hidden (fp16)
__device__ __half g_z2 [S_TOT*Hh];
__device__ float  g_g1 [P_TOT*Hh];
__device__ float  g_g2 [P_TOT*Hh];
__device__ float  g_agg[P_TOT*OUTC];
__device__ float  g_h1 [P_TOT*OUTC];
__device__ float  g_h2 [P_TOT*OUTC];
__device__ int    g_idx[S_TOT];
__device__ float  d_stats[8*256];   // [slot][ch sums | sumsq]

__device__ __forceinline__ unsigned tf32r(float f) {
    unsigned r; asm("cvt.rna.tf32.f32 %0, %1;" : "=r"(r) : "f"(f)); return r;
}
#define MMA_TF32(d, a, b) asm volatile( \
    "mma.sync.aligned.m16n8k8.row.col.f32.tf32.tf32.f32 " \
    "{%0,%1,%2,%3}, {%4,%5,%6,%7}, {%8,%9}, {%0,%1,%2,%3};" \
    : "+f"(d[0]),"+f"(d[1]),"+f"(d[2]),"+f"(d[3]) \
    : "r"(a[0]),"r"(a[1]),"r"(a[2]),"r"(a[3]), "r"(b[0]),"r"(b[1]))
#define MMA_F16(d, a, b) asm volatile( \
    "mma.sync.aligned.m16n8k16.row.col.f32.f16.f16.f32 " \
    "{%0,%1,%2,%3}, {%4,%5,%6,%7}, {%8,%9}, {%0,%1,%2,%3};" \
    : "+f"(d[0]),"+f"(d[1]),"+f"(d[2]),"+f"(d[3]) \
    : "r"(a[0]),"r"(a[1]),"r"(a[2]),"r"(a[3]), "r"(b[0]),"r"(b[1]))

__device__ __forceinline__ unsigned pack_h2(float a, float b) {
    __half2 h = __floats2half2_rn(a, b);
    return *(unsigned*)&h;
}

__global__ void zero_stats_kernel() {
    int t = blockIdx.x*256 + threadIdx.x;
    if (t < 8*256) d_stats[t] = 0.f;
}

// ---------------- KNN ---------------------------------------------------------
#define KNN_T    128
#define KNN_TILE 512
__global__ void knn_kernel(const float* __restrict__ xyz) {
    int b = blockIdx.y;
    int n = blockIdx.x*KNN_T + threadIdx.x;
    const float* xb = xyz + b*Nn*3;
    float qx = xb[n*3+0], qy = xb[n*3+1], qz = xb[n*3+2];
    float m2x = -2.f*qx, m2y = -2.f*qy, m2z = -2.f*qz;
    float bd[16]; int bi[16];
#pragma unroll
    for (int t=0;t<16;t++){ bd[t]=3.4e38f; bi[t]=0; }
    __shared__ float4 sp[KNN_TILE];
    for (int tile=0; tile<Nn; tile+=KNN_TILE) {
        __syncthreads();
        for (int t=threadIdx.x; t<KNN_TILE; t+=KNN_T) {
            int j = tile + t;
            float x = xb[j*3+0], y = xb[j*3+1], z = xb[j*3+2];
            float w = x*x; w = fmaf(y,y,w); w = fmaf(z,z,w);
            sp[t] = make_float4(x, y, z, w);
        }
        __syncthreads();
#pragma unroll 8
        for (int jj=0; jj<KNN_TILE; jj++) {
            float4 c = sp[jj];
            float d = fmaf(c.x, m2x, fmaf(c.y, m2y, fmaf(c.z, m2z, c.w)));
            if (d < bd[15]) {
                bd[15]=d; bi[15]=tile+jj;
#pragma unroll
                for (int t=15;t>0;t--) {
                    if (bd[t] < bd[t-1]) {
                        float td=bd[t]; bd[t]=bd[t-1]; bd[t-1]=td;
                        int   ti=bi[t]; bi[t]=bi[t-1]; bi[t-1]=ti;
                    }
                }
            }
        }
    }
    int base = (b*Nn + n)*Kk;
#pragma unroll
    for (int t=0;t<16;t++) g_idx[base+t] = bi[t];
}

// ---------------- LSE (3xTF32): enc[40] @ [w1|w2] -> y1,y2 fp16 (+stats) ------
#define LSE_TILES 16
__global__ void lse_mma_kernel(const float* __restrict__ xyz, const float* __restrict__ feat,
                               const float* __restrict__ w1, const float* __restrict__ w2,
                               __half* __restrict__ y1, __half* __restrict__ y2) {
    extern __shared__ unsigned lsh[];
    unsigned* encHi = lsh;              // [64][44]
    unsigned* encLo = lsh + 64*44;
    unsigned* wHi   = lsh + 2*64*44;    // [128][44]
    unsigned* wLo   = wHi + 128*44;
    __shared__ float ssS[128], sqS[128];
    int tid = threadIdx.x;              // 256
    for (int i=tid; i<128*44; i+=256) { wHi[i]=0u; wLo[i]=0u; }
    for (int i=tid; i<64*44;  i+=256) { encHi[i]=0u; encLo[i]=0u; }
    if (tid < 128) { ssS[tid]=0.f; sqS[tid]=0.f; }
    __syncthreads();
    for (int i=tid; i<128*CE; i+=256) {
        int n = i/CE, k = i - n*CE;
        float v = (n < 64) ? w1[n*CE+k] : w2[(n-64)*CE+k];
        unsigned hi = tf32r(v);
        wHi[n*44+k] = hi;
        wLo[n*44+k] = tf32r(v - __uint_as_float(hi));
    }
    int w = tid>>5, lane = tid&31, g = lane>>2, t4 = lane&3;
    int wM = w&1, wN = w>>1;
    int sOffW = wM*32, nOffW = wN*32;
    int sl = tid>>2, gq = tid&3;
    float stS[8]={0,0,0,0,0,0,0,0}, stQ[8]={0,0,0,0,0,0,0,0};
    __syncthreads();
    for (int tile=0; tile<LSE_TILES; tile++) {
        int base = (blockIdx.x*LSE_TILES + tile)*64;
        {   // build enc tile (4 threads per sample), hi/lo split
            int s = base + sl;
            int b = s >> 17;
            int n = (s >> 4) & (Nn-1);
            int j = g_idx[s];
            const float4* fp = (const float4*)(feat + (size_t)(b*Nn + j)*Cc + gq*8);
            float4 v0 = fp[0], v1 = fp[1];
            unsigned* eh = &encHi[sl*44 + 4 + gq*8];
            unsigned* el = &encLo[sl*44 + 4 + gq*8];
            float vv[8] = {v0.x,v0.y,v0.z,v0.w, v1.x,v1.y,v1.z,v1.w};
#pragma unroll
            for (int q=0;q<8;q++) {
                unsigned hi = tf32r(vv[q]);
                eh[q] = hi; el[q] = tf32r(vv[q] - __uint_as_float(hi));
            }
            if (gq == 0) {
                const float* pj = xyz + (size_t)(b*Nn + j)*3;
                const float* pn = xyz + (size_t)(b*Nn + n)*3;
                float dx=pj[0]-pn[0], dy=pj[1]-pn[1], dz=pj[2]-pn[2];
                float dd = dx*dx; dd=fmaf(dy,dy,dd); dd=fmaf(dz,dz,dd);
                float e4[4] = {dx, dy, dz, sqrtf(fmaxf(dd,1e-12f))};
#pragma unroll
                for (int q=0;q<4;q++) {
                    unsigned hi = tf32r(e4[q]);
                    encHi[sl*44+q] = hi;
                    encLo[sl*44+q] = tf32r(e4[q] - __uint_as_float(hi));
                }
            }
        }
        __syncthreads();
        float acc[2][4][4];
#pragma unroll
        for (int m=0;m<2;m++)
#pragma unroll
        for (int n=0;n<4;n++)
#pragma unroll
        for (int c=0;c<4;c++) acc[m][n][c]=0.f;
#pragma unroll
        for (int kk=0; kk<5; kk++) {
            int k0 = kk*8;
            unsigned aH[2][4], aL[2][4], bH[4][2], bL[4][2];
#pragma unroll
            for (int m=0;m<2;m++) {
                int r0 = (sOffW + m*16 + g)*44 + k0 + t4;
                aH[m][0]=encHi[r0]; aH[m][1]=encHi[r0+8*44];
                aH[m][2]=encHi[r0+4]; aH[m][3]=encHi[r0+8*44+4];
                aL[m][0]=encLo[r0]; aL[m][1]=encLo[r0+8*44];
                aL[m][2]=encLo[r0+4]; aL[m][3]=encLo[r0+8*44+4];
            }
#pragma unroll
            for (int n=0;n<4;n++) {
                int rb = (nOffW + n*8 + g)*44 + k0 + t4;
                bH[n][0]=wHi[rb]; bH[n][1]=wHi[rb+4];
                bL[n][0]=wLo[rb]; bL[n][1]=wLo[rb+4];
            }
#pragma unroll
            for (int m=0;m<2;m++)
#pragma unroll
            for (int n=0;n<4;n++) {
                MMA_TF32(acc[m][n], aL[m], bH[n]);
                MMA_TF32(acc[m][n], aH[m], bL[n]);
                MMA_TF32(acc[m][n], aH[m], bH[n]);
            }
        }
#pragma unroll
        for (int m=0;m<2;m++)
#pragma unroll
        for (int n=0;n<4;n++) {
            int row = base + sOffW + m*16 + g;
            int col = nOffW + n*8 + 2*t4;
            __half* dst = (col < 64) ? y1 : y2;
            int cc = col & 63;
            __half2 h0 = __floats2half2_rn(acc[m][n][0], acc[m][n][1]);
            __half2 h1 = __floats2half2_rn(acc[m][n][2], acc[m][n][3]);
            *(__half2*)&dst[(size_t)row*Hh + cc]     = h0;
            *(__half2*)&dst[(size_t)(row+8)*Hh + cc] = h1;
            stS[n*2  ] += acc[m][n][0] + acc[m][n][2];
            stS[n*2+1] += acc[m][n][1] + acc[m][n][3];
            stQ[n*2  ] = fmaf(acc[m][n][0],acc[m][n][0], fmaf(acc[m][n][2],acc[m][n][2], stQ[n*2  ]));
            stQ[n*2+1] = fmaf(acc[m][n][1],acc[m][n][1], fmaf(acc[m][n][3],acc[m][n][3], stQ[n*2+1]));
        }
        __syncthreads();
    }
#pragma unroll
    for (int n=0;n<4;n++)
#pragma unroll
    for (int p=0;p<2;p++) {
        int col = nOffW + n*8 + 2*t4 + p;
        atomicAdd(&ssS[col], stS[n*2+p]);
        atomicAdd(&sqS[col], stQ[n*2+p]);
    }
    __syncthreads();
    if (tid < 128) {
        int slot = (tid < 64) ? 0 : 3;
        int ch = tid & 63;
        atomicAdd(&d_stats[slot*256 + ch],      ssS[tid]);
        atomicAdd(&d_stats[slot*256 + 64 + ch], sqS[tid]);
    }
}

// ------- xz (fp16 MMA): z = relu(bn(y)) @ sw1^T, both branches (grid.y) ------
#define XZ_TILES 8
__global__ void xz_mma_kernel(const __half* __restrict__ y1, const __half* __restrict__ y2,
                              __half* __restrict__ z1, __half* __restrict__ z2,
                              const float* __restrict__ w1b, const float* __restrict__ w2b) {
    int br = blockIdx.y;
    const __half* src = br ? y2 : y1;
    __half*       dst = br ? z2 : z1;
    const float*  sw1 = br ? w2b : w1b;
    int slot_y = br ? 3 : 0, slot_z = br ? 4 : 1;
    __shared__ unsigned xH[128*36];     // half2 [s][k2]
    __shared__ unsigned wH[64*36];      // half2 [n][k2]
    __shared__ float mS[64], rS[64], ssS[64], sqS[64];
    int tid = threadIdx.x;              // 256
    for (int i=tid; i<64*32; i+=256) {
        int n = i>>5, k2 = i&31;
        wH[n*36+k2] = pack_h2(sw1[n*64+2*k2], sw1[n*64+2*k2+1]);
    }
    if (tid < 64) {
        float m = d_stats[slot_y*256+tid]*INV_S;
        float v = d_stats[slot_y*256+64+tid]*INV_S - m*m;
        mS[tid]=m; rS[tid]=rsqrtf(v+1e-5f);
        ssS[tid]=0.f; sqS[tid]=0.f;
    }
    int w = tid>>5, lane = tid&31, g = lane>>2, t4 = lane&3;
    int wM = w&3, wN = w>>2;
    int sOffW = wM*32, nOffW = wN*32;
    float stS[8]={0,0,0,0,0,0,0,0}, stQ[8]={0,0,0,0,0,0,0,0};
    __syncthreads();
    for (int tile=0; tile<XZ_TILES; tile++) {
        int base = (blockIdx.x*XZ_TILES + tile)*128;
        for (int i=tid; i<128*32; i+=256) {
            int s = i>>5, q = i&31, c = q*2;
            __half2 hv = ((const __half2*)(src + (size_t)(base+s)*Hh))[q];
            float2 f = __half22float2(hv);
            f.x = fmaxf((f.x-mS[c  ])*rS[c  ], 0.f);
            f.y = fmaxf((f.y-mS[c+1])*rS[c+1], 0.f);
            xH[s*36+q] = pack_h2(f.x, f.y);
        }
        __syncthreads();
        float acc[2][4][4];
#pragma unroll
        for (int m=0;m<2;m++)
#pragma unroll
        for (int n=0;n<4;n++)
#pragma unroll
        for (int c=0;c<4;c++) acc[m][n][c]=0.f;
#pragma unroll
        for (int kk=0; kk<4; kk++) {
            int k0 = kk*8;
            unsigned a[2][4], b[4][2];
#pragma unroll
            for (int m=0;m<2;m++) {
                int r0 = (sOffW + m*16 + g)*36 + k0 + t4;
                a[m][0]=xH[r0]; a[m][1]=xH[r0+8*36];
                a[m][2]=xH[r0+4]; a[m][3]=xH[r0+8*36+4];
            }
#pragma unroll
            for (int n=0;n<4;n++) {
                int rb = (nOffW + n*8 + g)*36 + k0 + t4;
                b[n][0]=wH[rb]; b[n][1]=wH[rb+4];
            }
#pragma unroll
            for (int m=0;m<2;m++)
#pragma unroll
            for (int n=0;n<4;n++) MMA_F16(acc[m][n], a[m], b[n]);
        }
#pragma unroll
        for (int m=0;m<2;m++)
#pragma unroll
        for (int n=0;n<4;n++) {
            int row = base + sOffW + m*16 + g;
            int col = nOffW + n*8 + 2*t4;
            __half2 h0 = __floats2half2_rn(acc[m][n][0], acc[m][n][1]);
            __half2 h1 = __floats2half2_rn(acc[m][n][2], acc[m][n][3]);
            *(__half2*)&dst[(size_t)row*Hh + col]     = h0;
            *(__half2*)&dst[(size_t)(row+8)*Hh + col] = h1;
            stS[n*2  ] += acc[m][n][0] + acc[m][n][2];
            stS[n*2+1] += acc[m][n][1] + acc[m][n][3];
            stQ[n*2  ] = fmaf(acc[m][n][0],acc[m][n][0], fmaf(acc[m][n][2],acc[m][n][2], stQ[n*2  ]));
            stQ[n*2+1] = fmaf(acc[m][n][1],acc[m][n][1], fmaf(acc[m][n][3],acc[m][n][3], stQ[n*2+1]));
        }
        __syncthreads();
    }
#pragma unroll
    for (int n=0;n<4;n++)
#pragma unroll
    for (int p=0;p<2;p++) {
        int col = nOffW + n*8 + 2*t4 + p;
        atomicAdd(&ssS[col], stS[n*2+p]);
        atomicAdd(&sqS[col], stQ[n*2+p]);
    }
    __syncthreads();
    if (tid < 64) {
        atomicAdd(&d_stats[slot_z*256 + tid],      ssS[tid]);
        atomicAdd(&d_stats[slot_z*256 + 64 + tid], sqS[tid]);
    }
}

// ------- attentive pool (both branches via grid.y) -----------------------------
#define POOL_PTS   4
#define POOL_ITERS 32
__global__ void pool_kernel(const __half* __restrict__ x1, const __half* __restrict__ zz1,
                            float* __restrict__ gg1,
                            const float* __restrict__ sw2a, const float* __restrict__ sb2a,
                            const float* __restrict__ mwa,
                            const __half* __restrict__ x2, const __half* __restrict__ zz2,
                            float* __restrict__ gg2,
                            const float* __restrict__ sw2b, const float* __restrict__ sb2b,
                            const float* __restrict__ mwb) {
    int br = blockIdx.y;
    const __half* gx = br ? x2 : x1;
    const __half* gz = br ? zz2 : zz1;
    float*        gg = br ? gg2 : gg1;
    const float* sw2 = br ? sw2b : sw2a;
    const float* sb2 = br ? sb2b : sb2a;
    const float* mw  = br ? mwb  : mwa;
    int slot_y = br ? 3 : 0, slot_z = br ? 4 : 1, slot_g = br ? 5 : 2;
    __shared__ float mwT[Hh*Hh];
    __shared__ float xt[POOL_PTS][Kk*Hh];
    __shared__ float sc[POOL_PTS][Kk];
    __shared__ float featS[POOL_PTS][Hh];
    __shared__ float myS[64], ryS[64], mzS[64], rzS[64], sw2S[64];
    __shared__ float ss[64], sq[64];
    int tid = threadIdx.x;              // 256
    for (int t=tid; t<Hh*Hh; t+=256) { int oo=t>>6, cc=t&63; mwT[cc*Hh+oo]=mw[t]; }
    if (tid < 64) {
        float m = d_stats[slot_y*256+tid]*INV_S;
        float v = d_stats[slot_y*256+64+tid]*INV_S - m*m;
        myS[tid]=m; ryS[tid]=rsqrtf(v+1e-5f);
        m = d_stats[slot_z*256+tid]*INV_S;
        v = d_stats[slot_z*256+64+tid]*INV_S - m*m;
        mzS[tid]=m; rzS[tid]=rsqrtf(v+1e-5f);
        sw2S[tid]=sw2[tid]; ss[tid]=0.f; sq[tid]=0.f;
    }
    float sb = sb2[0];
    int pp = tid>>6, o = tid&63;
    int pq = tid>>6, kq = (tid>>2)&15, cg = tid&3;
    float gS = 0.f, gQ = 0.f;
    __syncthreads();
    for (int it=0; it<POOL_ITERS; it++) {
        int p0 = (blockIdx.x*POOL_ITERS + it)*POOL_PTS;
        const uint4* xsrc = (const uint4*)(gx + (size_t)p0*Kk*Hh);
        for (int t=tid; t<POOL_PTS*Kk*Hh/8; t+=256) {    // 512 uint4 = 8 halves each
            uint4 u = xsrc[t];
            int pt = t>>7, r = t&127;
            int c = (r&7)*8;
            __half2* hp = (__half2*)&u;
            float2 f0 = __half22float2(hp[0]);
            float2 f1 = __half22float2(hp[1]);
            float2 f2 = __half22float2(hp[2]);
            float2 f3 = __half22float2(hp[3]);
            float4 o0, o1;
            o0.x = fmaxf((f0.x-myS[c  ])*ryS[c  ],0.f);
            o0.y = fmaxf((f0.y-myS[c+1])*ryS[c+1],0.f);
            o0.z = fmaxf((f1.x-myS[c+2])*ryS[c+2],0.f);
            o0.w = fmaxf((f1.y-myS[c+3])*ryS[c+3],0.f);
            o1.x = fmaxf((f2.x-myS[c+4])*ryS[c+4],0.f);
            o1.y = fmaxf((f2.y-myS[c+5])*ryS[c+5],0.f);
            o1.z = fmaxf((f3.x-myS[c+6])*ryS[c+6],0.f);
            o1.w = fmaxf((f3.y-myS[c+7])*ryS[c+7],0.f);
            ((float4*)xt[pt])[2*r]   = o0;
            ((float4*)xt[pt])[2*r+1] = o1;
        }
        {   // scores: 128 score-threads (pq,kq,cg), 16 channels each, from fp16 z
            const uint4* zp = (const uint4*)(gz + (size_t)(p0+pq)*Kk*Hh + kq*Hh + cg*16);
            float sacc = 0.f;
#pragma unroll
            for (int h=0; h<2; h++) {
                uint4 u = zp[h];
                __half2* hp = (__half2*)&u;
#pragma unroll
                for (int q=0; q<4; q++) {
                    float2 f = __half22float2(hp[q]);
                    int c = cg*16 + h*8 + q*2;
                    sacc += fmaxf((f.x-mzS[c  ])*rzS[c  ],0.f)*sw2S[c  ];
                    sacc += fmaxf((f.y-mzS[c+1])*rzS[c+1],0.f)*sw2S[c+1];
                }
            }
            sacc += __shfl_xor_sync(0xffffffffu, sacc, 1, 4);
            sacc += __shfl_xor_sync(0xffffffffu, sacc, 2, 4);
            if (cg == 0) sc[pq][kq] = sacc + sb;
        }
        __syncthreads();
        float mx = sc[pp][0];
#pragma unroll
        for (int k=1;k<16;k++) mx = fmaxf(mx, sc[pp][k]);
        float pk[16], den=0.f;
#pragma unroll
        for (int k=0;k<16;k++){ pk[k]=__expf(sc[pp][k]-mx); den+=pk[k]; }
        float inv = 1.f/den;
        float feat = 0.f;
#pragma unroll
        for (int k=0;k<16;k++) feat = fmaf(xt[pp][k*Hh+o], pk[k], feat);
        feat *= inv;
        featS[pp][o] = feat;
        __syncthreads();
        float gv = 0.f;
#pragma unroll
        for (int c=0;c<Hh;c++) gv = fmaf(featS[pp][c], mwT[c*Hh+o], gv);
        gg[(size_t)(p0+pp)*Hh + o] = gv;
        gS += gv; gQ = fmaf(gv, gv, gQ);
        __syncthreads();
    }
    atomicAdd(&ss[o], gS); atomicAdd(&sq[o], gQ);
    __syncthreads();
    if (tid < 64) {
        atomicAdd(&d_stats[slot_g*256 + tid],      ss[tid]);
        atomicAdd(&d_stats[slot_g*256 + 64 + tid], sq[tid]);
    }
}

// ------- DRB matmul (split-A tf32): out = relu(bn(src)) @ w^T (+stats) --------
// mode0: src = [g1|g2] with per-branch BN (slots 2,5); also writes g_agg.
// mode1: src = g_h1 with BN slot 6.
__global__ void drb_mma_kernel(const float* __restrict__ s1, const float* __restrict__ s2,
                               float* __restrict__ dst, const float* __restrict__ wmat,
                               int mode) {
    extern __shared__ unsigned sh[];
    unsigned* xHi = sh;                  // [128][132]
    unsigned* xLo = sh + 128*132;
    unsigned* wS  = sh + 2*128*132;      // [128][132]
    __shared__ float mS[OUTC], rS[OUTC], ssS[OUTC], sqS[OUTC];
    int slot_out = (mode==0) ? 6 : 7;
    int tid = threadIdx.x;               // 512
    for (int i=tid; i<OUTC*OUTC; i+=512) {
        int n = i>>7, k = i&127;
        wS[n*132+k] = tf32r(wmat[i]);
    }
    if (tid < 128) {
        ssS[tid]=0.f; sqS[tid]=0.f;
        float m, v;
        if (mode == 0) {
            int slot = (tid < 64) ? 2 : 5;
            int ch = tid & 63;
            m = d_stats[slot*256+ch]*INV_P;
            v = d_stats[slot*256+64+ch]*INV_P - m*m;
        } else {
            m = d_stats[6*256+tid]*INV_P;
            v = d_stats[6*256+128+tid]*INV_P - m*m;
        }
        mS[tid]=m; rS[tid]=rsqrtf(v+1e-5f);
    }
    int w = tid>>5, lane = tid&31, g = lane>>2, t4 = lane&3;
    int wM = w&3, wN = w>>2;
    int sOffW = wM*32, nOffW = wN*32;
    int base = blockIdx.x*128;
    __syncthreads();
    for (int i=tid; i<128*32; i+=512) {
        int s = i>>5, q = i&31, c = q*4;
        float4 v;
        if (mode == 0) {
            if (c < 64) v = ((const float4*)(s1 + (size_t)(base+s)*Hh))[q];
            else        v = ((const float4*)(s2 + (size_t)(base+s)*Hh))[q-16];
        } else {
            v = ((const float4*)(s1 + (size_t)(base+s)*OUTC))[q];
        }
        v.x = fmaxf((v.x-mS[c  ])*rS[c  ], 0.f);
        v.y = fmaxf((v.y-mS[c+1])*rS[c+1], 0.f);
        v.z = fmaxf((v.z-mS[c+2])*rS[c+2], 0.f);
        v.w = fmaxf((v.w-mS[c+3])*rS[c+3], 0.f);
        if (mode == 0) *(float4*)&g_agg[(size_t)(base+s)*OUTC + c] = v;
        float vv[4] = {v.x, v.y, v.z, v.w};
#pragma unroll
        for (int j=0;j<4;j++) {
            unsigned hi = tf32r(vv[j]);
            xHi[s*132 + c + j] = hi;
            xLo[s*132 + c + j] = tf32r(vv[j] - __uint_as_float(hi));
        }
    }
    __syncthreads();
    float acc[2][4][4];
#pragma unroll
    for (int m=0;m<2;m++)
#pragma unroll
    for (int n=0;n<4;n++)
#pragma unroll
    for (int c=0;c<4;c++) acc[m][n][c]=0.f;
#pragma unroll
    for (int kk=0; kk<16; kk++) {
        int k0 = kk*8;
        unsigned aH[2][4], aL[2][4], b[4][2];
#pragma unroll
        for (int m=0;m<2;m++) {
            int r0 = (sOffW + m*16 + g)*132 + k0 + t4;
            aH[m][0]=xHi[r0]; aH[m][1]=xHi[r0+8*132];
            aH[m][2]=xHi[r0+4]; aH[m][3]=xHi[r0+8*132+4];
            aL[m][0]=xLo[r0]; aL[m][1]=xLo[r0+8*132];
            aL[m][2]=xLo[r0+4]; aL[m][3]=xLo[r0+8*132+4];
        }
#pragma unroll
        for (int n=0;n<4;n++) {
            int rb = (nOffW + n*8 + g)*132 + k0 + t4;
            b[n][0]=wS[rb]; b[n][1]=wS[rb+4];
        }
#pragma unroll
        for (int m=0;m<2;m++)
#pragma unroll
        for (int n=0;n<4;n++) {
            MMA_TF32(acc[m][n], aL[m], b[n]);
            MMA_TF32(acc[m][n], aH[m], b[n]);
        }
    }
    float stS[8]={0,0,0,0,0,0,0,0}, stQ[8]={0,0,0,0,0,0,0,0};
#pragma unroll
    for (int m=0;m<2;m++)
#pragma unroll
    for (int n=0;n<4;n++) {
        int row = base + sOffW + m*16 + g;
        int col = nOffW + n*8 + 2*t4;
        *(float2*)&dst[(size_t)row*OUTC + col]     = make_float2(acc[m][n][0], acc[m][n][1]);
        *(float2*)&dst[(size_t)(row+8)*OUTC + col] = make_float2(acc[m][n][2], acc[m][n][3]);
        stS[n*2  ] += acc[m][n][0] + acc[m][n][2];
        stS[n*2+1] += acc[m][n][1] + acc[m][n][3];
        stQ[n*2  ] = fmaf(acc[m][n][0],acc[m][n][0], fmaf(acc[m][n][2],acc[m][n][2], stQ[n*2  ]));
        stQ[n*2+1] = fmaf(acc[m][n][1],acc[m][n][1], fmaf(acc[m][n][3],acc[m][n][3], stQ[n*2+1]));
    }
#pragma unroll
    for (int n=0;n<4;n++)
#pragma unroll
    for (int p=0;p<2;p++) {
        int col = nOffW + n*8 + 2*t4 + p;
        atomicAdd(&ssS[col], stS[n*2+p]);
        atomicAdd(&sqS[col], stQ[n*2+p]);
    }
    __syncthreads();
    if (tid < 128) {
        atomicAdd(&d_stats[slot_out*256 + tid],       ssS[tid]);
        atomicAdd(&d_stats[slot_out*256 + 128 + tid], sqS[tid]);
    }
}

// ------- out = relu(bn(h2) + agg) ---------------------------------------------
__global__ void final_kernel(float* __restrict__ out) {
    __shared__ float mS[128], rS[128];
    int tid = threadIdx.x;
    if (tid < 128) {
        float m = d_stats[7*256+tid]*INV_P;
        float v = d_stats[7*256+128+tid]*INV_P - m*m;
        mS[tid]=m; rS[tid]=rsqrtf(v+1e-5f);
    }
    __syncthreads();
    for (int t = blockIdx.x*256 + tid; t < P_TOT*32; t += gridDim.x*256) {
        int q = t & 31, c = q*4;
        float4 h = ((const float4*)g_h2)[t];
        float4 a = ((const float4*)g_agg)[t];
        float4 o;
        o.x = fmaxf((h.x-mS[c  ])*rS[c  ] + a.x, 0.f);
        o.y = fmaxf((h.y-mS[c+1])*rS[c+1] + a.y, 0.f);
        o.z = fmaxf((h.z-mS[c+2])*rS[c+2] + a.z, 0.f);
        o.w = fmaxf((h.w-mS[c+3])*rS[c+3] + a.w, 0.f);
        ((float4*)out)[t] = o;
    }
}

// ------------------------------ launch ----------------------------------------
extern "C" void kernel_launch(void* const* d_in, const int* in_sizes, int n_in,
                              void* d_out, int out_size) {
    const float* xyz     = (const float*)d_in[0];
    const float* feat    = (const float*)d_in[1];
    const float* w_lse1  = (const float*)d_in[2];
    const float* w_lse2  = (const float*)d_in[3];
    const float* ap1_sw1 = (const float*)d_in[4];
    const float* ap1_sw2 = (const float*)d_in[5];
    const float* ap1_sb2 = (const float*)d_in[6];
    const float* ap1_mw  = (const float*)d_in[7];
    const float* ap2_sw1 = (const float*)d_in[8];
    const float* ap2_sw2 = (const float*)d_in[9];
    const float* ap2_sb2 = (const float*)d_in[10];
    const float* ap2_mw  = (const float*)d_in[11];
    const float* drb_w1  = (const float*)d_in[12];
    const float* drb_w2  = (const float*)d_in[13];
    float* out = (float*)d_out;

    size_t lse_smem = (size_t)(2*64*44 + 2*128*44) * 4;   // 67.6 KB
    size_t drb_smem = (size_t)(3*128*132) * 4;            // 198 KB
    cudaFuncSetAttribute(lse_mma_kernel, cudaFuncAttributeMaxDynamicSharedMemorySize, (int)lse_smem);
    cudaFuncSetAttribute(drb_mma_kernel, cudaFuncAttributeMaxDynamicSharedMemorySize, (int)drb_smem);

    __half *py1, *py2, *pz1, *pz2;
    float *pg1, *pg2, *ph1, *ph2;
    cudaGetSymbolAddress((void**)&py1, g_y1);
    cudaGetSymbolAddress((void**)&py2, g_y2);
    cudaGetSymbolAddress((void**)&pz1, g_z1);
    cudaGetSymbolAddress((void**)&pz2, g_z2);
    cudaGetSymbolAddress((void**)&pg1, g_g1);
    cudaGetSymbolAddress((void**)&pg2, g_g2);
    cudaGetSymbolAddress((void**)&ph1, g_h1);
    cudaGetSymbolAddress((void**)&ph2, g_h2);

    zero_stats_kernel<<<8,256>>>();                                        // 0
    knn_kernel<<<dim3(Nn/KNN_T, Bz), KNN_T>>>(xyz);                        // 1
    lse_mma_kernel<<<512,256,lse_smem>>>(xyz, feat, w_lse1, w_lse2, py1, py2); // 2
    xz_mma_kernel<<<dim3(512,2),256>>>(py1, py2, pz1, pz2, ap1_sw1, ap2_sw1); // 3
    pool_kernel<<<dim3(256,2),256>>>(py1, pz1, pg1, ap1_sw2, ap1_sb2, ap1_mw,
                                     py2, pz2, pg2, ap2_sw2, ap2_sb2, ap2_mw); // 4
    drb_mma_kernel<<<256,512,drb_smem>>>(pg1, pg2, ph1, drb_w1, 0);        // 5 <- ncu
    drb_mma_kernel<<<256,512,drb_smem>>>(ph1, ph1, ph2, drb_w2, 1);        // 6
    final_kernel<<<512,256>>>(out);                                        // 7
}

// round 7
// speedup vs baseline: 2.5437x; 1.1333x over previous
#include <cuda_runtime.h>
#include <cuda_fp16.h>
#include <math.h>

#define Bz   4
#define Nn   8192
#define Cc   32
#define Kk   16
#define Hh   64
#define OUTC 128
#define CE   36
#define S_TOT (Bz*Nn*Kk)        // 524288
#define P_TOT (Bz*Nn)           // 32768
#define INV_S (1.f/524288.f)
#define INV_P (1.f/32768.f)

// ---------------- scratch -----------------------------------------------------
__device__ __half g_y1 [S_TOT*Hh];
__device__ __half g_y2 [S_TOT*Hh];
__device__ __half g_z1 [S_TOT*Hh];
__device__ __half g_z2 [S_TOT*Hh];
__device__ float  g_g1 [P_TOT*Hh];
__device__ float  g_g2 [P_TOT*Hh];
__device__ float  g_agg[P_TOT*OUTC];
__device__ float  g_h1 [P_TOT*OUTC];
__device__ float  g_h2 [P_TOT*OUTC];
__device__ int    g_idx[S_TOT];
__device__ float  d_stats[8*256];

__device__ __forceinline__ unsigned tf32r(float f) {
    unsigned r; asm("cvt.rna.tf32.f32 %0, %1;" : "=r"(r) : "f"(f)); return r;
}
#define MMA_TF32(d, a, b) asm volatile( \
    "mma.sync.aligned.m16n8k8.row.col.f32.tf32.tf32.f32 " \
    "{%0,%1,%2,%3}, {%4,%5,%6,%7}, {%8,%9}, {%0,%1,%2,%3};" \
    : "+f"(d[0]),"+f"(d[1]),"+f"(d[2]),"+f"(d[3]) \
    : "r"(a[0]),"r"(a[1]),"r"(a[2]),"r"(a[3]), "r"(b[0]),"r"(b[1]))
#define MMA_F16(d, a, b) asm volatile( \
    "mma.sync.aligned.m16n8k16.row.col.f32.f16.f16.f32 " \
    "{%0,%1,%2,%3}, {%4,%5,%6,%7}, {%8,%9}, {%0,%1,%2,%3};" \
    : "+f"(d[0]),"+f"(d[1]),"+f"(d[2]),"+f"(d[3]) \
    : "r"(a[0]),"r"(a[1]),"r"(a[2]),"r"(a[3]), "r"(b[0]),"r"(b[1]))

__device__ __forceinline__ unsigned pack_h2(float a, float b) {
    __half2 h = __floats2half2_rn(a, b);
    return *(unsigned*)&h;
}
// split (a,b) into fp16 hi + fp16 lo(residual)
__device__ __forceinline__ void split_h2(float a, float b, unsigned &hi, unsigned &lo) {
    __half ha = __float2half_rn(a), hb = __float2half_rn(b);
    float la = a - __half2float(ha), lb = b - __half2float(hb);
    __half2 h = __halves2half2(ha, hb);
    __half2 l = __floats2half2_rn(la, lb);
    hi = *(unsigned*)&h; lo = *(unsigned*)&l;
}

__global__ void zero_stats_kernel() {
    int t = blockIdx.x*256 + threadIdx.x;
    if (t < 8*256) d_stats[t] = 0.f;
}

// ---------------- KNN ---------------------------------------------------------
#define KNN_T    128
#define KNN_TILE 512
__global__ void knn_kernel(const float* __restrict__ xyz) {
    int b = blockIdx.y;
    int n = blockIdx.x*KNN_T + threadIdx.x;
    const float* xb = xyz + b*Nn*3;
    float qx = xb[n*3+0], qy = xb[n*3+1], qz = xb[n*3+2];
    float m2x = -2.f*qx, m2y = -2.f*qy, m2z = -2.f*qz;
    float bd[16]; int bi[16];
#pragma unroll
    for (int t=0;t<16;t++){ bd[t]=3.4e38f; bi[t]=0; }
    __shared__ float4 sp[KNN_TILE];
    for (int tile=0; tile<Nn; tile+=KNN_TILE) {
        __syncthreads();
        for (int t=threadIdx.x; t<KNN_TILE; t+=KNN_T) {
            int j = tile + t;
            float x = xb[j*3+0], y = xb[j*3+1], z = xb[j*3+2];
            float w = x*x; w = fmaf(y,y,w); w = fmaf(z,z,w);
            sp[t] = make_float4(x, y, z, w);
        }
        __syncthreads();
#pragma unroll 8
        for (int jj=0; jj<KNN_TILE; jj++) {
            float4 c = sp[jj];
            float d = fmaf(c.x, m2x, fmaf(c.y, m2y, fmaf(c.z, m2z, c.w)));
            if (d < bd[15]) {
                bd[15]=d; bi[15]=tile+jj;
#pragma unroll
                for (int t=15;t>0;t--) {
                    if (bd[t] < bd[t-1]) {
                        float td=bd[t]; bd[t]=bd[t-1]; bd[t-1]=td;
                        int   ti=bi[t]; bi[t]=bi[t-1]; bi[t-1]=ti;
                    }
                }
            }
        }
    }
    int base = (b*Nn + n)*Kk;
#pragma unroll
    for (int t=0;t<16;t++) g_idx[base+t] = bi[t];
}

// ---------------- LSE (3xFP16 split): enc[48] @ [w1|w2] -> y1,y2 (+stats) -----
// smem half2 arrays, stride 28 (data half2 0..23 = channels 0..47; 36 real)
#define LSE_TILES 16
__global__ void lse_mma_kernel(const float* __restrict__ xyz, const float* __restrict__ feat,
                               const float* __restrict__ w1, const float* __restrict__ w2,
                               __half* __restrict__ y1, __half* __restrict__ y2) {
    __shared__ unsigned encH[64*28], encL[64*28];
    __shared__ unsigned wH[128*28], wL[128*28];
    __shared__ float ssS[128], sqS[128];
    int tid = threadIdx.x;              // 256
    for (int i=tid; i<64*28;  i+=256) { encH[i]=0u; encL[i]=0u; }
    for (int i=tid; i<128*28; i+=256) { wH[i]=0u; wL[i]=0u; }
    if (tid < 128) { ssS[tid]=0.f; sqS[tid]=0.f; }
    __syncthreads();
    for (int i=tid; i<128*18; i+=256) {
        int n = i/18, k2 = i - n*18;
        const float* wsrc = (n < 64) ? (w1 + n*CE) : (w2 + (n-64)*CE);
        unsigned hi, lo;
        split_h2(wsrc[2*k2], wsrc[2*k2+1], hi, lo);
        wH[n*28+k2] = hi; wL[n*28+k2] = lo;
    }
    int w = tid>>5, lane = tid&31, g = lane>>2, t4 = lane&3;
    int wM = w&1, wN = w>>1;
    int sOffW = wM*32, nOffW = wN*32;
    int sl = tid>>2, gq = tid&3;
    float stS[8]={0,0,0,0,0,0,0,0}, stQ[8]={0,0,0,0,0,0,0,0};
    __syncthreads();
    for (int tile=0; tile<LSE_TILES; tile++) {
        int base = (blockIdx.x*LSE_TILES + tile)*64;
        {   // build enc tile: 4 threads/sample, hi/lo fp16 split
            int s = base + sl;
            int b = s >> 17;
            int n = (s >> 4) & (Nn-1);
            int j = g_idx[s];
            const float4* fp = (const float4*)(feat + (size_t)(b*Nn + j)*Cc + gq*8);
            float4 v0 = fp[0], v1 = fp[1];
            int h0 = sl*28 + 2 + gq*4;
            unsigned hi, lo;
            split_h2(v0.x, v0.y, hi, lo); encH[h0  ]=hi; encL[h0  ]=lo;
            split_h2(v0.z, v0.w, hi, lo); encH[h0+1]=hi; encL[h0+1]=lo;
            split_h2(v1.x, v1.y, hi, lo); encH[h0+2]=hi; encL[h0+2]=lo;
            split_h2(v1.z, v1.w, hi, lo); encH[h0+3]=hi; encL[h0+3]=lo;
            if (gq == 0) {
                const float* pj = xyz + (size_t)(b*Nn + j)*3;
                const float* pn = xyz + (size_t)(b*Nn + n)*3;
                float dx=pj[0]-pn[0], dy=pj[1]-pn[1], dz=pj[2]-pn[2];
                float dd = dx*dx; dd=fmaf(dy,dy,dd); dd=fmaf(dz,dz,dd);
                float ds = sqrtf(fmaxf(dd,1e-12f));
                split_h2(dx, dy, hi, lo); encH[sl*28  ]=hi; encL[sl*28  ]=lo;
                split_h2(dz, ds, hi, lo); encH[sl*28+1]=hi; encL[sl*28+1]=lo;
            }
        }
        __syncthreads();
        float acc[2][4][4];
#pragma unroll
        for (int m=0;m<2;m++)
#pragma unroll
        for (int n=0;n<4;n++)
#pragma unroll
        for (int c=0;c<4;c++) acc[m][n][c]=0.f;
#pragma unroll
        for (int kk=0; kk<3; kk++) {
            int k0 = kk*8;
            unsigned aH[2][4], aL[2][4], bH[4][2], bL[4][2];
#pragma unroll
            for (int m=0;m<2;m++) {
                int r0 = (sOffW + m*16 + g)*28 + k0 + t4;
                aH[m][0]=encH[r0]; aH[m][1]=encH[r0+8*28];
                aH[m][2]=encH[r0+4]; aH[m][3]=encH[r0+8*28+4];
                aL[m][0]=encL[r0]; aL[m][1]=encL[r0+8*28];
                aL[m][2]=encL[r0+4]; aL[m][3]=encL[r0+8*28+4];
            }
#pragma unroll
            for (int n=0;n<4;n++) {
                int rb = (nOffW + n*8 + g)*28 + k0 + t4;
                bH[n][0]=wH[rb]; bH[n][1]=wH[rb+4];
                bL[n][0]=wL[rb]; bL[n][1]=wL[rb+4];
            }
#pragma unroll
            for (int m=0;m<2;m++)
#pragma unroll
            for (int n=0;n<4;n++) {
                MMA_F16(acc[m][n], aL[m], bH[n]);
                MMA_F16(acc[m][n], aH[m], bL[n]);
                MMA_F16(acc[m][n], aH[m], bH[n]);
            }
        }
#pragma unroll
        for (int m=0;m<2;m++)
#pragma unroll
        for (int n=0;n<4;n++) {
            int row = base + sOffW + m*16 + g;
            int col = nOffW + n*8 + 2*t4;
            __half* dst = (col < 64) ? y1 : y2;
            int cc = col & 63;
            __half2 h0 = __floats2half2_rn(acc[m][n][0], acc[m][n][1]);
            __half2 h1 = __floats2half2_rn(acc[m][n][2], acc[m][n][3]);
            *(__half2*)&dst[(size_t)row*Hh + cc]     = h0;
            *(__half2*)&dst[(size_t)(row+8)*Hh + cc] = h1;
            stS[n*2  ] += acc[m][n][0] + acc[m][n][2];
            stS[n*2+1] += acc[m][n][1] + acc[m][n][3];
            stQ[n*2  ] = fmaf(acc[m][n][0],acc[m][n][0], fmaf(acc[m][n][2],acc[m][n][2], stQ[n*2  ]));
            stQ[n*2+1] = fmaf(acc[m][n][1],acc[m][n][1], fmaf(acc[m][n][3],acc[m][n][3], stQ[n*2+1]));
        }
        __syncthreads();
    }
#pragma unroll
    for (int n=0;n<4;n++)
#pragma unroll
    for (int p=0;p<2;p++) {
        int col = nOffW + n*8 + 2*t4 + p;
        atomicAdd(&ssS[col], stS[n*2+p]);
        atomicAdd(&sqS[col], stQ[n*2+p]);
    }
    __syncthreads();
    if (tid < 128) {
        int slot = (tid < 64) ? 0 : 3;
        int ch = tid & 63;
        atomicAdd(&d_stats[slot*256 + ch],      ssS[tid]);
        atomicAdd(&d_stats[slot*256 + 64 + ch], sqS[tid]);
    }
}

// ------- xz (fp16 MMA, reg-prefetch pipelined) ---------------------------------
#define XZ_TILES 8
__global__ void xz_mma_kernel(const __half* __restrict__ y1, const __half* __restrict__ y2,
                              __half* __restrict__ z1, __half* __restrict__ z2,
                              const float* __restrict__ w1b, const float* __restrict__ w2b) {
    int br = blockIdx.y;
    const __half* src = br ? y2 : y1;
    __half*       dst = br ? z2 : z1;
    const float*  sw1 = br ? w2b : w1b;
    int slot_y = br ? 3 : 0, slot_z = br ? 4 : 1;
    __shared__ unsigned xH[128*36];
    __shared__ unsigned wHs[64*36];
    __shared__ float mS[64], rS[64], ssS[64], sqS[64];
    int tid = threadIdx.x;              // 256
    for (int i=tid; i<64*32; i+=256) {
        int n = i>>5, k2 = i&31;
        wHs[n*36+k2] = pack_h2(sw1[n*64+2*k2], sw1[n*64+2*k2+1]);
    }
    if (tid < 64) {
        float m = d_stats[slot_y*256+tid]*INV_S;
        float v = d_stats[slot_y*256+64+tid]*INV_S - m*m;
        mS[tid]=m; rS[tid]=rsqrtf(v+1e-5f);
        ssS[tid]=0.f; sqS[tid]=0.f;
    }
    int w = tid>>5, lane = tid&31, g = lane>>2, t4 = lane&3;
    int wM = w&3, wN = w>>2;
    int sOffW = wM*32, nOffW = wN*32;
    float stS[8]={0,0,0,0,0,0,0,0}, stQ[8]={0,0,0,0,0,0,0,0};
    const uint4* sv = (const uint4*)src;    // 8 uint4 per 64-ch row
    size_t base0 = (size_t)blockIdx.x*XZ_TILES*128;
    uint4 pf[4];
#pragma unroll
    for (int j=0;j<4;j++) pf[j] = sv[base0*8 + tid*4 + j];
    __syncthreads();                        // mS/rS + weights ready
    for (int tile=0; tile<XZ_TILES; tile++) {
        // transform prefetched tile into smem
#pragma unroll
        for (int j=0;j<4;j++) {
            int e = tid*4 + j;
            int s = e>>3, q = e&7, c = q*8;
            __half2* hp = (__half2*)&pf[j];
            float2 f0 = __half22float2(hp[0]);
            float2 f1 = __half22float2(hp[1]);
            float2 f2 = __half22float2(hp[2]);
            float2 f3 = __half22float2(hp[3]);
            uint4 u;
            u.x = pack_h2(fmaxf((f0.x-mS[c  ])*rS[c  ],0.f), fmaxf((f0.y-mS[c+1])*rS[c+1],0.f));
            u.y = pack_h2(fmaxf((f1.x-mS[c+2])*rS[c+2],0.f), fmaxf((f1.y-mS[c+3])*rS[c+3],0.f));
            u.z = pack_h2(fmaxf((f2.x-mS[c+4])*rS[c+4],0.f), fmaxf((f2.y-mS[c+5])*rS[c+5],0.f));
            u.w = pack_h2(fmaxf((f3.x-mS[c+6])*rS[c+6],0.f), fmaxf((f3.y-mS[c+7])*rS[c+7],0.f));
            *(uint4*)&xH[s*36 + q*4] = u;
        }
        __syncthreads();
        if (tile+1 < XZ_TILES) {
            size_t nb = (base0 + (size_t)(tile+1)*128)*8;
#pragma unroll
            for (int j=0;j<4;j++) pf[j] = sv[nb + tid*4 + j];
        }
        int base = (int)(base0 + tile*128);
        float acc[2][4][4];
#pragma unroll
        for (int m=0;m<2;m++)
#pragma unroll
        for (int n=0;n<4;n++)
#pragma unroll
        for (int c=0;c<4;c++) acc[m][n][c]=0.f;
#pragma unroll
        for (int kk=0; kk<4; kk++) {
            int k0 = kk*8;
            unsigned a[2][4], b[4][2];
#pragma unroll
            for (int m=0;m<2;m++) {
                int r0 = (sOffW + m*16 + g)*36 + k0 + t4;
                a[m][0]=xH[r0]; a[m][1]=xH[r0+8*36];
                a[m][2]=xH[r0+4]; a[m][3]=xH[r0+8*36+4];
            }
#pragma unroll
            for (int n=0;n<4;n++) {
                int rb = (nOffW + n*8 + g)*36 + k0 + t4;
                b[n][0]=wHs[rb]; b[n][1]=wHs[rb+4];
            }
#pragma unroll
            for (int m=0;m<2;m++)
#pragma unroll
            for (int n=0;n<4;n++) MMA_F16(acc[m][n], a[m], b[n]);
        }
#pragma unroll
        for (int m=0;m<2;m++)
#pragma unroll
        for (int n=0;n<4;n++) {
            int row = base + sOffW + m*16 + g;
            int col = nOffW + n*8 + 2*t4;
            __half2 h0 = __floats2half2_rn(acc[m][n][0], acc[m][n][1]);
            __half2 h1 = __floats2half2_rn(acc[m][n][2], acc[m][n][3]);
            *(__half2*)&dst[(size_t)row*Hh + col]     = h0;
            *(__half2*)&dst[(size_t)(row+8)*Hh + col] = h1;
            stS[n*2  ] += acc[m][n][0] + acc[m][n][2];
            stS[n*2+1] += acc[m][n][1] + acc[m][n][3];
            stQ[n*2  ] = fmaf(acc[m][n][0],acc[m][n][0], fmaf(acc[m][n][2],acc[m][n][2], stQ[n*2  ]));
            stQ[n*2+1] = fmaf(acc[m][n][1],acc[m][n][1], fmaf(acc[m][n][3],acc[m][n][3], stQ[n*2+1]));
        }
        __syncthreads();
    }
#pragma unroll
    for (int n=0;n<4;n++)
#pragma unroll
    for (int p=0;p<2;p++) {
        int col = nOffW + n*8 + 2*t4 + p;
        atomicAdd(&ssS[col], stS[n*2+p]);
        atomicAdd(&sqS[col], stQ[n*2+p]);
    }
    __syncthreads();
    if (tid < 64) {
        atomicAdd(&d_stats[slot_z*256 + tid],      ssS[tid]);
        atomicAdd(&d_stats[slot_z*256 + 64 + tid], sqS[tid]);
    }
}

// ------- attentive pool: warp-per-point, no block barriers ---------------------
#define POOL_PW 8   // points per warp
__global__ void pool_kernel(const __half* __restrict__ x1, const __half* __restrict__ zz1,
                            float* __restrict__ gg1,
                            const float* __restrict__ sw2a, const float* __restrict__ mwa,
                            const __half* __restrict__ x2, const __half* __restrict__ zz2,
                            float* __restrict__ gg2,
                            const float* __restrict__ sw2b, const float* __restrict__ mwb) {
    int br = blockIdx.y;
    const __half* gx = br ? x2 : x1;
    const __half* gz = br ? zz2 : zz1;
    float*        gg = br ? gg2 : gg1;
    const float* sw2 = br ? sw2b : sw2a;
    const float* mw  = br ? mwb  : mwa;
    int slot_y = br ? 3 : 0, slot_z = br ? 4 : 1, slot_g = br ? 5 : 2;
    __shared__ float mwT[Hh*Hh];        // [c][o]
    __shared__ float featS[8][Hh];
    __shared__ float myS[64], ryS[64], mzS[64], rzS[64], sw2S[64];
    __shared__ float ss[64], sq[64];
    int tid = threadIdx.x;              // 256
    for (int i=tid; i<Hh*Hh; i+=256) { int o=i>>6, c=i&63; mwT[c*Hh+o]=mw[i]; }
    if (tid < 64) {
        float m = d_stats[slot_y*256+tid]*INV_S;
        float v = d_stats[slot_y*256+64+tid]*INV_S - m*m;
        myS[tid]=m; ryS[tid]=rsqrtf(v+1e-5f);
        m = d_stats[slot_z*256+tid]*INV_S;
        v = d_stats[slot_z*256+64+tid]*INV_S - m*m;
        mzS[tid]=m; rzS[tid]=rsqrtf(v+1e-5f);
        sw2S[tid]=sw2[tid]; ss[tid]=0.f; sq[tid]=0.f;
    }
    __syncthreads();
    int w = tid>>5, lane = tid&31, kg = lane>>3, cg = lane&7;
    int c0 = cg*8;
    float sSa=0.f, sQa=0.f, sSb=0.f, sQb=0.f;
    int p0 = (blockIdx.x*8 + w)*POOL_PW;
    for (int it=0; it<POOL_PW; it++) {
        int p = p0 + it;
        const uint4* xp = (const uint4*)(gx + (size_t)p*Kk*Hh);
        const uint4* zp = (const uint4*)(gz + (size_t)p*Kk*Hh);
        float xv[4][8];
        float sp[4];
#pragma unroll
        for (int i=0;i<4;i++) {
            int row = kg*4 + i;
            uint4 ux = xp[row*8 + cg];
            uint4 uz = zp[row*8 + cg];
            __half2* hx = (__half2*)&ux;
            __half2* hz = (__half2*)&uz;
            float s = 0.f;
#pragma unroll
            for (int q=0;q<4;q++) {
                float2 fx = __half22float2(hx[q]);
                float2 fz = __half22float2(hz[q]);
                int c = c0 + 2*q;
                xv[i][2*q  ] = fmaxf((fx.x-myS[c  ])*ryS[c  ], 0.f);
                xv[i][2*q+1] = fmaxf((fx.y-myS[c+1])*ryS[c+1], 0.f);
                s += fmaxf((fz.x-mzS[c  ])*rzS[c  ],0.f)*sw2S[c  ];
                s += fmaxf((fz.y-mzS[c+1])*rzS[c+1],0.f)*sw2S[c+1];
            }
            sp[i] = s;
        }
        // reduce scores over channel-groups (lanes sharing kg)
#pragma unroll
        for (int i=0;i<4;i++) {
            sp[i] += __shfl_xor_sync(0xffffffffu, sp[i], 1);
            sp[i] += __shfl_xor_sync(0xffffffffu, sp[i], 2);
            sp[i] += __shfl_xor_sync(0xffffffffu, sp[i], 4);
        }
        // softmax over all 16 k (each k replicated on 8 lanes)
        float mx = fmaxf(fmaxf(sp[0],sp[1]), fmaxf(sp[2],sp[3]));
#pragma unroll
        for (int msk=1; msk<32; msk<<=1) mx = fmaxf(mx, __shfl_xor_sync(0xffffffffu, mx, msk));
        float e0=__expf(sp[0]-mx), e1=__expf(sp[1]-mx), e2=__expf(sp[2]-mx), e3=__expf(sp[3]-mx);
        float ls = e0+e1+e2+e3;
#pragma unroll
        for (int msk=1; msk<32; msk<<=1) ls += __shfl_xor_sync(0xffffffffu, ls, msk);
        float inv = 8.f/ls;                 // each k counted 8x
        float pk[4] = {e0*inv, e1*inv, e2*inv, e3*inv};
        // feat partial over this lane's 4 k rows
        float fpv[8];
#pragma unroll
        for (int j=0;j<8;j++) {
            float f = xv[0][j]*pk[0];
            f = fmaf(xv[1][j], pk[1], f);
            f = fmaf(xv[2][j], pk[2], f);
            f = fmaf(xv[3][j], pk[3], f);
            fpv[j] = f;
        }
        // reduce across k-groups
#pragma unroll
        for (int j=0;j<8;j++) {
            fpv[j] += __shfl_xor_sync(0xffffffffu, fpv[j], 8);
            fpv[j] += __shfl_xor_sync(0xffffffffu, fpv[j], 16);
        }
        if (kg == 0) {
#pragma unroll
            for (int j=0;j<8;j++) featS[w][c0+j] = fpv[j];
        }
        __syncwarp();
        // g = feat @ mw^T : lane computes channels (lane, lane+32)
        float ga=0.f, gb=0.f;
#pragma unroll 16
        for (int c=0;c<Hh;c++) {
            float f = featS[w][c];
            ga = fmaf(f, mwT[c*Hh + lane],      ga);
            gb = fmaf(f, mwT[c*Hh + 32 + lane], gb);
        }
        gg[(size_t)p*Hh + lane]      = ga;
        gg[(size_t)p*Hh + 32 + lane] = gb;
        sSa += ga; sQa = fmaf(ga,ga,sQa);
        sSb += gb; sQb = fmaf(gb,gb,sQb);
        __syncwarp();
    }
    atomicAdd(&ss[lane], sSa);      atomicAdd(&sq[lane], sQa);
    atomicAdd(&ss[32+lane], sSb);   atomicAdd(&sq[32+lane], sQb);
    __syncthreads();
    if (tid < 64) {
        atomicAdd(&d_stats[slot_g*256 + tid],      ss[tid]);
        atomicAdd(&d_stats[slot_g*256 + 64 + tid], sq[tid]);
    }
}

// ------- DRB matmul (split-A tf32) ---------------------------------------------
__global__ void drb_mma_kernel(const float* __restrict__ s1, const float* __restrict__ s2,
                               float* __restrict__ dst, const float* __restrict__ wmat,
                               int mode) {
    extern __shared__ unsigned sh[];
    unsigned* xHi = sh;                  // [128][132]
    unsigned* xLo = sh + 128*132;
    unsigned* wS  = sh + 2*128*132;      // [128][132]
    __shared__ float mS[OUTC], rS[OUTC], ssS[OUTC], sqS[OUTC];
    int slot_out = (mode==0) ? 6 : 7;
    int tid = threadIdx.x;               // 512
    for (int i=tid; i<OUTC*OUTC; i+=512) {
        int n = i>>7, k = i&127;
        wS[n*132+k] = tf32r(wmat[i]);
    }
    if (tid < 128) {
        ssS[tid]=0.f; sqS[tid]=0.f;
        float m, v;
        if (mode == 0) {
            int slot = (tid < 64) ? 2 : 5;
            int ch = tid & 63;
            m = d_stats[slot*256+ch]*INV_P;
            v = d_stats[slot*256+64+ch]*INV_P - m*m;
        } else {
            m = d_stats[6*256+tid]*INV_P;
            v = d_stats[6*256+128+tid]*INV_P - m*m;
        }
        mS[tid]=m; rS[tid]=rsqrtf(v+1e-5f);
    }
    int w = tid>>5, lane = tid&31, g = lane>>2, t4 = lane&3;
    int wM = w&3, wN = w>>2;
    int sOffW = wM*32, nOffW = wN*32;
    int base = blockIdx.x*128;
    __syncthreads();
    for (int i=tid; i<128*32; i+=512) {
        int s = i>>5, q = i&31, c = q*4;
        float4 v;
        if (mode == 0) {
            if (c < 64) v = ((const float4*)(s1 + (size_t)(base+s)*Hh))[q];
            else        v = ((const float4*)(s2 + (size_t)(base+s)*Hh))[q-16];
        } else {
            v = ((const float4*)(s1 + (size_t)(base+s)*OUTC))[q];
        }
        v.x = fmaxf((v.x-mS[c  ])*rS[c  ], 0.f);
        v.y = fmaxf((v.y-mS[c+1])*rS[c+1], 0.f);
        v.z = fmaxf((v.z-mS[c+2])*rS[c+2], 0.f);
        v.w = fmaxf((v.w-mS[c+3])*rS[c+3], 0.f);
        if (mode == 0) *(float4*)&g_agg[(size_t)(base+s)*OUTC + c] = v;
        float vv[4] = {v.x, v.y, v.z, v.w};
#pragma unroll
        for (int j=0;j<4;j++) {
            unsigned hi = tf32r(vv[j]);
            xHi[s*132 + c + j] = hi;
            xLo[s*132 + c + j] = tf32r(vv[j] - __uint_as_float(hi));
        }
    }
    __syncthreads();
    float acc[2][4][4];
#pragma unroll
    for (int m=0;m<2;m++)
#pragma unroll
    for (int n=0;n<4;n++)
#pragma unroll
    for (int c=0;c<4;c++) acc[m][n][c]=0.f;
#pragma unroll
    for (int kk=0; kk<16; kk++) {
        int k0 = kk*8;
        unsigned aH[2][4], aL[2][4], b[4][2];
#pragma unroll
        for (int m=0;m<2;m++) {
            int r0 = (sOffW + m*16 + g)*132 + k0 + t4;
            aH[m][0]=xHi[r0]; aH[m][1]=xHi[r0+8*132];
            aH[m][2]=xHi[r0+4]; aH[m][3]=xHi[r0+8*132+4];
            aL[m][0]=xLo[r0]; aL[m][1]=xLo[r0+8*132];
            aL[m][2]=xLo[r0+4]; aL[m][3]=xLo[r0+8*132+4];
        }
#pragma unroll
        for (int n=0;n<4;n++) {
            int rb = (nOffW + n*8 + g)*132 + k0 + t4;
            b[n][0]=wS[rb]; b[n][1]=wS[rb+4];
        }
#pragma unroll
        for (int m=0;m<2;m++)
#pragma unroll
        for (int n=0;n<4;n++) {
            MMA_TF32(acc[m][n], aL[m], b[n]);
            MMA_TF32(acc[m][n], aH[m], b[n]);
        }
    }
    float stS[8]={0,0,0,0,0,0,0,0}, stQ[8]={0,0,0,0,0,0,0,0};
#pragma unroll
    for (int m=0;m<2;m++)
#pragma unroll
    for (int n=0;n<4;n++) {
        int row = base + sOffW + m*16 + g;
        int col = nOffW + n*8 + 2*t4;
        *(float2*)&dst[(size_t)row*OUTC + col]     = make_float2(acc[m][n][0], acc[m][n][1]);
        *(float2*)&dst[(size_t)(row+8)*OUTC + col] = make_float2(acc[m][n][2], acc[m][n][3]);
        stS[n*2  ] += acc[m][n][0] + acc[m][n][2];
        stS[n*2+1] += acc[m][n][1] + acc[m][n][3];
        stQ[n*2  ] = fmaf(acc[m][n][0],acc[m][n][0], fmaf(acc[m][n][2],acc[m][n][2], stQ[n*2  ]));
        stQ[n*2+1] = fmaf(acc[m][n][1],acc[m][n][1], fmaf(acc[m][n][3],acc[m][n][3], stQ[n*2+1]));
    }
#pragma unroll
    for (int n=0;n<4;n++)
#pragma unroll
    for (int p=0;p<2;p++) {
        int col = nOffW + n*8 + 2*t4 + p;
        atomicAdd(&ssS[col], stS[n*2+p]);
        atomicAdd(&sqS[col], stQ[n*2+p]);
    }
    __syncthreads();
    if (tid < 128) {
        atomicAdd(&d_stats[slot_out*256 + tid],       ssS[tid]);
        atomicAdd(&d_stats[slot_out*256 + 128 + tid], sqS[tid]);
    }
}

// ------- out = relu(bn(h2) + agg) ---------------------------------------------
__global__ void final_kernel(float* __restrict__ out) {
    __shared__ float mS[128], rS[128];
    int tid = threadIdx.x;
    if (tid < 128) {
        float m = d_stats[7*256+tid]*INV_P;
        float v = d_stats[7*256+128+tid]*INV_P - m*m;
        mS[tid]=m; rS[tid]=rsqrtf(v+1e-5f);
    }
    __syncthreads();
    for (int t = blockIdx.x*256 + tid; t < P_TOT*32; t += gridDim.x*256) {
        int q = t & 31, c = q*4;
        float4 h = ((const float4*)g_h2)[t];
        float4 a = ((const float4*)g_agg)[t];
        float4 o;
        o.x = fmaxf((h.x-mS[c  ])*rS[c  ] + a.x, 0.f);
        o.y = fmaxf((h.y-mS[c+1])*rS[c+1] + a.y, 0.f);
        o.z = fmaxf((h.z-mS[c+2])*rS[c+2] + a.z, 0.f);
        o.w = fmaxf((h.w-mS[c+3])*rS[c+3] + a.w, 0.f);
        ((float4*)out)[t] = o;
    }
}

// ------------------------------ launch ----------------------------------------
extern "C" void kernel_launch(void* const* d_in, const int* in_sizes, int n_in,
                              void* d_out, int out_size) {
    const float* xyz     = (const float*)d_in[0];
    const float* feat    = (const float*)d_in[1];
    const float* w_lse1  = (const float*)d_in[2];
    const float* w_lse2  = (const float*)d_in[3];
    const float* ap1_sw1 = (const float*)d_in[4];
    const float* ap1_sw2 = (const float*)d_in[5];
    const float* ap1_mw  = (const float*)d_in[7];
    const float* ap2_sw1 = (const float*)d_in[8];
    const float* ap2_sw2 = (const float*)d_in[9];
    const float* ap2_mw  = (const float*)d_in[11];
    const float* drb_w1  = (const float*)d_in[12];
    const float* drb_w2  = (const float*)d_in[13];
    float* out = (float*)d_out;

    size_t drb_smem = (size_t)(3*128*132) * 4;            // 198 KB
    cudaFuncSetAttribute(drb_mma_kernel, cudaFuncAttributeMaxDynamicSharedMemorySize, (int)drb_smem);

    __half *py1, *py2, *pz1, *pz2;
    float *pg1, *pg2, *ph1, *ph2;
    cudaGetSymbolAddress((void**)&py1, g_y1);
    cudaGetSymbolAddress((void**)&py2, g_y2);
    cudaGetSymbolAddress((void**)&pz1, g_z1);
    cudaGetSymbolAddress((void**)&pz2, g_z2);
    cudaGetSymbolAddress((void**)&pg1, g_g1);
    cudaGetSymbolAddress((void**)&pg2, g_g2);
    cudaGetSymbolAddress((void**)&ph1, g_h1);
    cudaGetSymbolAddress((void**)&ph2, g_h2);

    zero_stats_kernel<<<8,256>>>();
    knn_kernel<<<dim3(Nn/KNN_T, Bz), KNN_T>>>(xyz);
    lse_mma_kernel<<<512,256>>>(xyz, feat, w_lse1, w_lse2, py1, py2);
    xz_mma_kernel<<<dim3(512,2),256>>>(py1, py2, pz1, pz2, ap1_sw1, ap2_sw1);
    pool_kernel<<<dim3(512,2),256>>>(py1, pz1, pg1, ap1_sw2, ap1_mw,
                                     py2, pz2, pg2, ap2_sw2, ap2_mw);
    drb_mma_kernel<<<256,512,drb_smem>>>(pg1, pg2, ph1, drb_w1, 0);
    drb_mma_kernel<<<256,512,drb_smem>>>(ph1, ph1, ph2, drb_w2, 1);
    final_kernel<<<512,256>>>(out);
}

// round 8
// speedup vs baseline: 2.5953x; 1.0203x over previous
#include <cuda_runtime.h>
#include <cuda_fp16.h>
#include <math.h>

#define Bz   4
#define Nn   8192
#define Cc   32
#define Kk   16
#define Hh   64
#define OUTC 128
#define CE   36
#define S_TOT (Bz*Nn*Kk)        // 524288
#define P_TOT (Bz*Nn)           // 32768
#define INV_S (1.f/524288.f)
#define INV_P (1.f/32768.f)

// ---------------- scratch -----------------------------------------------------
__device__ __half g_y1 [S_TOT*Hh];
__device__ __half g_y2 [S_TOT*Hh];
__device__ __half g_z1 [S_TOT*Hh];
__device__ __half g_z2 [S_TOT*Hh];
__device__ float  g_g1 [P_TOT*Hh];
__device__ float  g_g2 [P_TOT*Hh];
__device__ float  g_agg[P_TOT*OUTC];
__device__ float  g_h1 [P_TOT*OUTC];
__device__ float  g_h2 [P_TOT*OUTC];
__device__ int    g_idx[S_TOT];
__device__ float  d_stats[8*256];

__device__ __forceinline__ unsigned tf32r(float f) {
    unsigned r; asm("cvt.rna.tf32.f32 %0, %1;" : "=r"(r) : "f"(f)); return r;
}
#define MMA_TF32(d, a, b) asm volatile( \
    "mma.sync.aligned.m16n8k8.row.col.f32.tf32.tf32.f32 " \
    "{%0,%1,%2,%3}, {%4,%5,%6,%7}, {%8,%9}, {%0,%1,%2,%3};" \
    : "+f"(d[0]),"+f"(d[1]),"+f"(d[2]),"+f"(d[3]) \
    : "r"(a[0]),"r"(a[1]),"r"(a[2]),"r"(a[3]), "r"(b[0]),"r"(b[1]))
#define MMA_F16(d, a, b) asm volatile( \
    "mma.sync.aligned.m16n8k16.row.col.f32.f16.f16.f32 " \
    "{%0,%1,%2,%3}, {%4,%5,%6,%7}, {%8,%9}, {%0,%1,%2,%3};" \
    : "+f"(d[0]),"+f"(d[1]),"+f"(d[2]),"+f"(d[3]) \
    : "r"(a[0]),"r"(a[1]),"r"(a[2]),"r"(a[3]), "r"(b[0]),"r"(b[1]))

__device__ __forceinline__ unsigned pack_h2(float a, float b) {
    __half2 h = __floats2half2_rn(a, b);
    return *(unsigned*)&h;
}
__device__ __forceinline__ void split_h2(float a, float b, unsigned &hi, unsigned &lo) {
    __half ha = __float2half_rn(a), hb = __float2half_rn(b);
    float la = a - __half2float(ha), lb = b - __half2float(hb);
    __half2 h = __halves2half2(ha, hb);
    __half2 l = __floats2half2_rn(la, lb);
    hi = *(unsigned*)&h; lo = *(unsigned*)&l;
}

__global__ void zero_stats_kernel() {
    int t = blockIdx.x*256 + threadIdx.x;
    if (t < 8*256) d_stats[t] = 0.f;
}

// ---------------- KNN ---------------------------------------------------------
#define KNN_T    128
#define KNN_TILE 1024
__global__ void knn_kernel(const float* __restrict__ xyz) {
    int b = blockIdx.y;
    int n = blockIdx.x*KNN_T + threadIdx.x;
    const float* xb = xyz + b*Nn*3;
    float qx = xb[n*3+0], qy = xb[n*3+1], qz = xb[n*3+2];
    float m2x = -2.f*qx, m2y = -2.f*qy, m2z = -2.f*qz;
    float bd[16]; int bi[16];
#pragma unroll
    for (int t=0;t<16;t++){ bd[t]=3.4e38f; bi[t]=0; }
    __shared__ float4 sp[KNN_TILE];
    for (int tile=0; tile<Nn; tile+=KNN_TILE) {
        __syncthreads();
        for (int t=threadIdx.x; t<KNN_TILE; t+=KNN_T) {
            int j = tile + t;
            float x = xb[j*3+0], y = xb[j*3+1], z = xb[j*3+2];
            float w = x*x; w = fmaf(y,y,w); w = fmaf(z,z,w);
            sp[t] = make_float4(x, y, z, w);
        }
        __syncthreads();
#pragma unroll 8
        for (int jj=0; jj<KNN_TILE; jj++) {
            float4 c = sp[jj];
            float d = fmaf(c.x, m2x, fmaf(c.y, m2y, fmaf(c.z, m2z, c.w)));
            if (d < bd[15]) {
                bd[15]=d; bi[15]=tile+jj;
#pragma unroll
                for (int t=15;t>0;t--) {
                    if (bd[t] < bd[t-1]) {
                        float td=bd[t]; bd[t]=bd[t-1]; bd[t-1]=td;
                        int   ti=bi[t]; bi[t]=bi[t-1]; bi[t-1]=ti;
                    }
                }
            }
        }
    }
    int base = (b*Nn + n)*Kk;
#pragma unroll
    for (int t=0;t<16;t++) g_idx[base+t] = bi[t];
}

// ---------------- LSE (3xFP16 split, pipelined gather) ------------------------
#define LSE_TILES 16
__global__ void lse_mma_kernel(const float* __restrict__ xyz, const float* __restrict__ feat,
                               const float* __restrict__ w1, const float* __restrict__ w2,
                               __half* __restrict__ y1, __half* __restrict__ y2) {
    __shared__ unsigned encH[64*28], encL[64*28];
    __shared__ unsigned wH[128*28], wL[128*28];
    __shared__ float ssS[128], sqS[128];
    int tid = threadIdx.x;              // 256
    for (int i=tid; i<64*28;  i+=256) { encH[i]=0u; encL[i]=0u; }
    for (int i=tid; i<128*28; i+=256) { wH[i]=0u; wL[i]=0u; }
    if (tid < 128) { ssS[tid]=0.f; sqS[tid]=0.f; }
    __syncthreads();
    for (int i=tid; i<128*18; i+=256) {
        int n = i/18, k2 = i - n*18;
        const float* wsrc = (n < 64) ? (w1 + n*CE) : (w2 + (n-64)*CE);
        unsigned hi, lo;
        split_h2(wsrc[2*k2], wsrc[2*k2+1], hi, lo);
        wH[n*28+k2] = hi; wL[n*28+k2] = lo;
    }
    int w = tid>>5, lane = tid&31, g = lane>>2, t4 = lane&3;
    int wM = w&1, wN = w>>1;
    int sOffW = wM*32, nOffW = wN*32;
    int sl = tid>>2, gq = tid&3;
    float stS[8]={0,0,0,0,0,0,0,0}, stQ[8]={0,0,0,0,0,0,0,0};

    // prefetch state
    float4 pv0, pv1;
    float aj0=0,aj1=0,aj2=0, an0=0,an1=0,an2=0;
#define LSE_LOAD(T) { \
    int s = (blockIdx.x*LSE_TILES + (T))*64 + sl; \
    int bb = s >> 17; \
    int nn2 = (s >> 4) & (Nn-1); \
    int j = g_idx[s]; \
    const float4* fp = (const float4*)(feat + (size_t)(bb*Nn + j)*Cc + gq*8); \
    pv0 = fp[0]; pv1 = fp[1]; \
    if (gq == 0) { \
        const float* pj = xyz + (size_t)(bb*Nn + j)*3; \
        const float* pn = xyz + (size_t)(bb*Nn + nn2)*3; \
        aj0=pj[0]; aj1=pj[1]; aj2=pj[2]; an0=pn[0]; an1=pn[1]; an2=pn[2]; \
    } }

    LSE_LOAD(0);
    __syncthreads();
    for (int tile=0; tile<LSE_TILES; tile++) {
        int base = (blockIdx.x*LSE_TILES + tile)*64;
        {   // stage prefetched data into smem (hi/lo fp16 split)
            int h0 = sl*28 + 2 + gq*4;
            unsigned hi, lo;
            split_h2(pv0.x, pv0.y, hi, lo); encH[h0  ]=hi; encL[h0  ]=lo;
            split_h2(pv0.z, pv0.w, hi, lo); encH[h0+1]=hi; encL[h0+1]=lo;
            split_h2(pv1.x, pv1.y, hi, lo); encH[h0+2]=hi; encL[h0+2]=lo;
            split_h2(pv1.z, pv1.w, hi, lo); encH[h0+3]=hi; encL[h0+3]=lo;
            if (gq == 0) {
                float dx=aj0-an0, dy=aj1-an1, dz=aj2-an2;
                float dd = dx*dx; dd=fmaf(dy,dy,dd); dd=fmaf(dz,dz,dd);
                float ds = sqrtf(fmaxf(dd,1e-12f));
                split_h2(dx, dy, hi, lo); encH[sl*28  ]=hi; encL[sl*28  ]=lo;
                split_h2(dz, ds, hi, lo); encH[sl*28+1]=hi; encL[sl*28+1]=lo;
            }
        }
        __syncthreads();
        if (tile+1 < LSE_TILES) LSE_LOAD(tile+1);   // overlaps MMA below
        float acc[2][4][4];
#pragma unroll
        for (int m=0;m<2;m++)
#pragma unroll
        for (int n=0;n<4;n++)
#pragma unroll
        for (int c=0;c<4;c++) acc[m][n][c]=0.f;
#pragma unroll
        for (int kk=0; kk<3; kk++) {
            int k0 = kk*8;
            unsigned aH[2][4], aL[2][4], bH[4][2], bL[4][2];
#pragma unroll
            for (int m=0;m<2;m++) {
                int r0 = (sOffW + m*16 + g)*28 + k0 + t4;
                aH[m][0]=encH[r0]; aH[m][1]=encH[r0+8*28];
                aH[m][2]=encH[r0+4]; aH[m][3]=encH[r0+8*28+4];
                aL[m][0]=encL[r0]; aL[m][1]=encL[r0+8*28];
                aL[m][2]=encL[r0+4]; aL[m][3]=encL[r0+8*28+4];
            }
#pragma unroll
            for (int n=0;n<4;n++) {
                int rb = (nOffW + n*8 + g)*28 + k0 + t4;
                bH[n][0]=wH[rb]; bH[n][1]=wH[rb+4];
                bL[n][0]=wL[rb]; bL[n][1]=wL[rb+4];
            }
#pragma unroll
            for (int m=0;m<2;m++)
#pragma unroll
            for (int n=0;n<4;n++) {
                MMA_F16(acc[m][n], aL[m], bH[n]);
                MMA_F16(acc[m][n], aH[m], bL[n]);
                MMA_F16(acc[m][n], aH[m], bH[n]);
            }
        }
#pragma unroll
        for (int m=0;m<2;m++)
#pragma unroll
        for (int n=0;n<4;n++) {
            int row = base + sOffW + m*16 + g;
            int col = nOffW + n*8 + 2*t4;
            __half* dst = (col < 64) ? y1 : y2;
            int cc = col & 63;
            __half2 h0 = __floats2half2_rn(acc[m][n][0], acc[m][n][1]);
            __half2 h1 = __floats2half2_rn(acc[m][n][2], acc[m][n][3]);
            *(__half2*)&dst[(size_t)row*Hh + cc]     = h0;
            *(__half2*)&dst[(size_t)(row+8)*Hh + cc] = h1;
            stS[n*2  ] += acc[m][n][0] + acc[m][n][2];
            stS[n*2+1] += acc[m][n][1] + acc[m][n][3];
            stQ[n*2  ] = fmaf(acc[m][n][0],acc[m][n][0], fmaf(acc[m][n][2],acc[m][n][2], stQ[n*2  ]));
            stQ[n*2+1] = fmaf(acc[m][n][1],acc[m][n][1], fmaf(acc[m][n][3],acc[m][n][3], stQ[n*2+1]));
        }
        __syncthreads();
    }
#pragma unroll
    for (int n=0;n<4;n++)
#pragma unroll
    for (int p=0;p<2;p++) {
        int col = nOffW + n*8 + 2*t4 + p;
        atomicAdd(&ssS[col], stS[n*2+p]);
        atomicAdd(&sqS[col], stQ[n*2+p]);
    }
    __syncthreads();
    if (tid < 128) {
        int slot = (tid < 64) ? 0 : 3;
        int ch = tid & 63;
        atomicAdd(&d_stats[slot*256 + ch],      ssS[tid]);
        atomicAdd(&d_stats[slot*256 + 64 + ch], sqS[tid]);
    }
}

// ------- xz (fp16 MMA, reg-prefetch + B-frags register-resident) ---------------
#define XZ_TILES 8
__global__ void xz_mma_kernel(const __half* __restrict__ y1, const __half* __restrict__ y2,
                              __half* __restrict__ z1, __half* __restrict__ z2,
                              const float* __restrict__ w1b, const float* __restrict__ w2b) {
    int br = blockIdx.y;
    const __half* src = br ? y2 : y1;
    __half*       dst = br ? z2 : z1;
    const float*  sw1 = br ? w2b : w1b;
    int slot_y = br ? 3 : 0, slot_z = br ? 4 : 1;
    __shared__ unsigned xH[128*36];
    __shared__ unsigned wHs[64*36];
    __shared__ float mS[64], rS[64], ssS[64], sqS[64];
    int tid = threadIdx.x;              // 256
    for (int i=tid; i<64*32; i+=256) {
        int n = i>>5, k2 = i&31;
        wHs[n*36+k2] = pack_h2(sw1[n*64+2*k2], sw1[n*64+2*k2+1]);
    }
    if (tid < 64) {
        float m = d_stats[slot_y*256+tid]*INV_S;
        float v = d_stats[slot_y*256+64+tid]*INV_S - m*m;
        mS[tid]=m; rS[tid]=rsqrtf(v+1e-5f);
        ssS[tid]=0.f; sqS[tid]=0.f;
    }
    int w = tid>>5, lane = tid&31, g = lane>>2, t4 = lane&3;
    int wM = w&3, wN = w>>2;
    int sOffW = wM*32, nOffW = wN*32;
    float stS[8]={0,0,0,0,0,0,0,0}, stQ[8]={0,0,0,0,0,0,0,0};
    const uint4* sv = (const uint4*)src;
    size_t base0 = (size_t)blockIdx.x*XZ_TILES*128;
    uint4 pf[4];
#pragma unroll
    for (int j=0;j<4;j++) pf[j] = sv[base0*8 + tid*4 + j];
    __syncthreads();                        // weights + stats staged
    // B fragments: load once, reuse across all tiles
    unsigned bR[4][4][2];
#pragma unroll
    for (int kk=0; kk<4; kk++)
#pragma unroll
    for (int n=0;n<4;n++) {
        int rb = (nOffW + n*8 + g)*36 + kk*8 + t4;
        bR[kk][n][0]=wHs[rb]; bR[kk][n][1]=wHs[rb+4];
    }
    for (int tile=0; tile<XZ_TILES; tile++) {
#pragma unroll
        for (int j=0;j<4;j++) {
            int e = tid*4 + j;
            int s = e>>3, q = e&7, c = q*8;
            __half2* hp = (__half2*)&pf[j];
            float2 f0 = __half22float2(hp[0]);
            float2 f1 = __half22float2(hp[1]);
            float2 f2 = __half22float2(hp[2]);
            float2 f3 = __half22float2(hp[3]);
            uint4 u;
            u.x = pack_h2(fmaxf((f0.x-mS[c  ])*rS[c  ],0.f), fmaxf((f0.y-mS[c+1])*rS[c+1],0.f));
            u.y = pack_h2(fmaxf((f1.x-mS[c+2])*rS[c+2],0.f), fmaxf((f1.y-mS[c+3])*rS[c+3],0.f));
            u.z = pack_h2(fmaxf((f2.x-mS[c+4])*rS[c+4],0.f), fmaxf((f2.y-mS[c+5])*rS[c+5],0.f));
            u.w = pack_h2(fmaxf((f3.x-mS[c+6])*rS[c+6],0.f), fmaxf((f3.y-mS[c+7])*rS[c+7],0.f));
            *(uint4*)&xH[s*36 + q*4] = u;
        }
        __syncthreads();
        if (tile+1 < XZ_TILES) {
            size_t nb = (base0 + (size_t)(tile+1)*128)*8;
#pragma unroll
            for (int j=0;j<4;j++) pf[j] = sv[nb + tid*4 + j];
        }
        int base = (int)(base0 + tile*128);
        float acc[2][4][4];
#pragma unroll
        for (int m=0;m<2;m++)
#pragma unroll
        for (int n=0;n<4;n++)
#pragma unroll
        for (int c=0;c<4;c++) acc[m][n][c]=0.f;
#pragma unroll
        for (int kk=0; kk<4; kk++) {
            int k0 = kk*8;
            unsigned a[2][4];
#pragma unroll
            for (int m=0;m<2;m++) {
                int r0 = (sOffW + m*16 + g)*36 + k0 + t4;
                a[m][0]=xH[r0]; a[m][1]=xH[r0+8*36];
                a[m][2]=xH[r0+4]; a[m][3]=xH[r0+8*36+4];
            }
#pragma unroll
            for (int m=0;m<2;m++)
#pragma unroll
            for (int n=0;n<4;n++) MMA_F16(acc[m][n], a[m], bR[kk][n]);
        }
#pragma unroll
        for (int m=0;m<2;m++)
#pragma unroll
        for (int n=0;n<4;n++) {
            int row = base + sOffW + m*16 + g;
            int col = nOffW + n*8 + 2*t4;
            __half2 h0 = __floats2half2_rn(acc[m][n][0], acc[m][n][1]);
            __half2 h1 = __floats2half2_rn(acc[m][n][2], acc[m][n][3]);
            *(__half2*)&dst[(size_t)row*Hh + col]     = h0;
            *(__half2*)&dst[(size_t)(row+8)*Hh + col] = h1;
            stS[n*2  ] += acc[m][n][0] + acc[m][n][2];
            stS[n*2+1] += acc[m][n][1] + acc[m][n][3];
            stQ[n*2  ] = fmaf(acc[m][n][0],acc[m][n][0], fmaf(acc[m][n][2],acc[m][n][2], stQ[n*2  ]));
            stQ[n*2+1] = fmaf(acc[m][n][1],acc[m][n][1], fmaf(acc[m][n][3],acc[m][n][3], stQ[n*2+1]));
        }
        __syncthreads();
    }
#pragma unroll
    for (int n=0;n<4;n++)
#pragma unroll
    for (int p=0;p<2;p++) {
        int col = nOffW + n*8 + 2*t4 + p;
        atomicAdd(&ssS[col], stS[n*2+p]);
        atomicAdd(&sqS[col], stQ[n*2+p]);
    }
    __syncthreads();
    if (tid < 64) {
        atomicAdd(&d_stats[slot_z*256 + tid],      ssS[tid]);
        atomicAdd(&d_stats[slot_z*256 + 64 + tid], sqS[tid]);
    }
}

// ------- attentive pool: warp-per-point ----------------------------------------
#define POOL_PW 8
__global__ void pool_kernel(const __half* __restrict__ x1, const __half* __restrict__ zz1,
                            float* __restrict__ gg1,
                            const float* __restrict__ sw2a, const float* __restrict__ mwa,
                            const __half* __restrict__ x2, const __half* __restrict__ zz2,
                            float* __restrict__ gg2,
                            const float* __restrict__ sw2b, const float* __restrict__ mwb) {
    int br = blockIdx.y;
    const __half* gx = br ? x2 : x1;
    const __half* gz = br ? zz2 : zz1;
    float*        gg = br ? gg2 : gg1;
    const float* sw2 = br ? sw2b : sw2a;
    const float* mw  = br ? mwb  : mwa;
    int slot_y = br ? 3 : 0, slot_z = br ? 4 : 1, slot_g = br ? 5 : 2;
    __shared__ float2 mw2[Hh*32];       // [c][lane] -> (mw[lane][c], mw[lane+32][c])
    __shared__ float featS[8][Hh];
    __shared__ float myS[64], ryS[64], mzS[64], rzS[64], sw2S[64];
    __shared__ float ss[64], sq[64];
    int tid = threadIdx.x;              // 256
    for (int i=tid; i<Hh*32; i+=256) {
        int c=i>>5, l=i&31;
        mw2[i] = make_float2(mw[l*Hh+c], mw[(l+32)*Hh+c]);
    }
    if (tid < 64) {
        float m = d_stats[slot_y*256+tid]*INV_S;
        float v = d_stats[slot_y*256+64+tid]*INV_S - m*m;
        myS[tid]=m; ryS[tid]=rsqrtf(v+1e-5f);
        m = d_stats[slot_z*256+tid]*INV_S;
        v = d_stats[slot_z*256+64+tid]*INV_S - m*m;
        mzS[tid]=m; rzS[tid]=rsqrtf(v+1e-5f);
        sw2S[tid]=sw2[tid]; ss[tid]=0.f; sq[tid]=0.f;
    }
    __syncthreads();
    int w = tid>>5, lane = tid&31, kg = lane>>3, cg = lane&7;
    int c0 = cg*8;
    float sSa=0.f, sQa=0.f, sSb=0.f, sQb=0.f;
    int p0 = (blockIdx.x*8 + w)*POOL_PW;
    for (int it=0; it<POOL_PW; it++) {
        int p = p0 + it;
        const uint4* xp = (const uint4*)(gx + (size_t)p*Kk*Hh);
        const uint4* zp = (const uint4*)(gz + (size_t)p*Kk*Hh);
        float xv[4][8];
        float sp[4];
#pragma unroll
        for (int i=0;i<4;i++) {
            int row = kg*4 + i;
            uint4 ux = xp[row*8 + cg];
            uint4 uz = zp[row*8 + cg];
            __half2* hx = (__half2*)&ux;
            __half2* hz = (__half2*)&uz;
            float s = 0.f;
#pragma unroll
            for (int q=0;q<4;q++) {
                float2 fx = __half22float2(hx[q]);
                float2 fz = __half22float2(hz[q]);
                int c = c0 + 2*q;
                xv[i][2*q  ] = fmaxf((fx.x-myS[c  ])*ryS[c  ], 0.f);
                xv[i][2*q+1] = fmaxf((fx.y-myS[c+1])*ryS[c+1], 0.f);
                s += fmaxf((fz.x-mzS[c  ])*rzS[c  ],0.f)*sw2S[c  ];
                s += fmaxf((fz.y-mzS[c+1])*rzS[c+1],0.f)*sw2S[c+1];
            }
            sp[i] = s;
        }
#pragma unroll
        for (int i=0;i<4;i++) {
            sp[i] += __shfl_xor_sync(0xffffffffu, sp[i], 1);
            sp[i] += __shfl_xor_sync(0xffffffffu, sp[i], 2);
            sp[i] += __shfl_xor_sync(0xffffffffu, sp[i], 4);
        }
        float mx = fmaxf(fmaxf(sp[0],sp[1]), fmaxf(sp[2],sp[3]));
#pragma unroll
        for (int msk=1; msk<32; msk<<=1) mx = fmaxf(mx, __shfl_xor_sync(0xffffffffu, mx, msk));
        float e0=__expf(sp[0]-mx), e1=__expf(sp[1]-mx), e2=__expf(sp[2]-mx), e3=__expf(sp[3]-mx);
        float ls = e0+e1+e2+e3;
#pragma unroll
        for (int msk=1; msk<32; msk<<=1) ls += __shfl_xor_sync(0xffffffffu, ls, msk);
        float inv = 8.f/ls;
        float pk[4] = {e0*inv, e1*inv, e2*inv, e3*inv};
        float fpv[8];
#pragma unroll
        for (int j=0;j<8;j++) {
            float f = xv[0][j]*pk[0];
            f = fmaf(xv[1][j], pk[1], f);
            f = fmaf(xv[2][j], pk[2], f);
            f = fmaf(xv[3][j], pk[3], f);
            fpv[j] = f;
        }
#pragma unroll
        for (int j=0;j<8;j++) {
            fpv[j] += __shfl_xor_sync(0xffffffffu, fpv[j], 8);
            fpv[j] += __shfl_xor_sync(0xffffffffu, fpv[j], 16);
        }
        if (kg == 0) {
#pragma unroll
            for (int j=0;j<8;j++) featS[w][c0+j] = fpv[j];
        }
        __syncwarp();
        float ga=0.f, gb=0.f;
#pragma unroll 16
        for (int c=0;c<Hh;c++) {
            float f = featS[w][c];
            float2 wv = mw2[c*32 + lane];
            ga = fmaf(f, wv.x, ga);
            gb = fmaf(f, wv.y, gb);
        }
        gg[(size_t)p*Hh + lane]      = ga;
        gg[(size_t)p*Hh + 32 + lane] = gb;
        sSa += ga; sQa = fmaf(ga,ga,sQa);
        sSb += gb; sQb = fmaf(gb,gb,sQb);
        __syncwarp();
    }
    atomicAdd(&ss[lane], sSa);      atomicAdd(&sq[lane], sQa);
    atomicAdd(&ss[32+lane], sSb);   atomicAdd(&sq[32+lane], sQb);
    __syncthreads();
    if (tid < 64) {
        atomicAdd(&d_stats[slot_g*256 + tid],      ss[tid]);
        atomicAdd(&d_stats[slot_g*256 + 64 + tid], sq[tid]);
    }
}

// ------- DRB matmul (split-A tf32) ---------------------------------------------
__global__ void drb_mma_kernel(const float* __restrict__ s1, const float* __restrict__ s2,
                               float* __restrict__ dst, const float* __restrict__ wmat,
                               int mode) {
    extern __shared__ unsigned sh[];
    unsigned* xHi = sh;                  // [128][132]
    unsigned* xLo = sh + 128*132;
    unsigned* wS  = sh + 2*128*132;      // [128][132]
    __shared__ float mS[OUTC], rS[OUTC], ssS[OUTC], sqS[OUTC];
    int slot_out = (mode==0) ? 6 : 7;
    int tid = threadIdx.x;               // 512
    for (int i=tid; i<OUTC*OUTC; i+=512) {
        int n = i>>7, k = i&127;
        wS[n*132+k] = tf32r(wmat[i]);
    }
    if (tid < 128) {
        ssS[tid]=0.f; sqS[tid]=0.f;
        float m, v;
        if (mode == 0) {
            int slot = (tid < 64) ? 2 : 5;
            int ch = tid & 63;
            m = d_stats[slot*256+ch]*INV_P;
            v = d_stats[slot*256+64+ch]*INV_P - m*m;
        } else {
            m = d_stats[6*256+tid]*INV_P;
            v = d_stats[6*256+128+tid]*INV_P - m*m;
        }
        mS[tid]=m; rS[tid]=rsqrtf(v+1e-5f);
    }
    int w = tid>>5, lane = tid&31, g = lane>>2, t4 = lane&3;
    int wM = w&3, wN = w>>2;
    int sOffW = wM*32, nOffW = wN*32;
    int base = blockIdx.x*128;
    __syncthreads();
    for (int i=tid; i<128*32; i+=512) {
        int s = i>>5, q = i&31, c = q*4;
        float4 v;
        if (mode == 0) {
            if (c < 64) v = ((const float4*)(s1 + (size_t)(base+s)*Hh))[q];
            else        v = ((const float4*)(s2 + (size_t)(base+s)*Hh))[q-16];
        } else {
            v = ((const float4*)(s1 + (size_t)(base+s)*OUTC))[q];
        }
        v.x = fmaxf((v.x-mS[c  ])*rS[c  ], 0.f);
        v.y = fmaxf((v.y-mS[c+1])*rS[c+1], 0.f);
        v.z = fmaxf((v.z-mS[c+2])*rS[c+2], 0.f);
        v.w = fmaxf((v.w-mS[c+3])*rS[c+3], 0.f);
        if (mode == 0) *(float4*)&g_agg[(size_t)(base+s)*OUTC + c] = v;
        float vv[4] = {v.x, v.y, v.z, v.w};
#pragma unroll
        for (int j=0;j<4;j++) {
            unsigned hi = tf32r(vv[j]);
            xHi[s*132 + c + j] = hi;
            xLo[s*132 + c + j] = tf32r(vv[j] - __uint_as_float(hi));
        }
    }
    __syncthreads();
    float acc[2][4][4];
#pragma unroll
    for (int m=0;m<2;m++)
#pragma unroll
    for (int n=0;n<4;n++)
#pragma unroll
    for (int c=0;c<4;c++) acc[m][n][c]=0.f;
#pragma unroll
    for (int kk=0; kk<16; kk++) {
        int k0 = kk*8;
        unsigned aH[2][4], aL[2][4], b[4][2];
#pragma unroll
        for (int m=0;m<2;m++) {
            int r0 = (sOffW + m*16 + g)*132 + k0 + t4;
            aH[m][0]=xHi[r0]; aH[m][1]=xHi[r0+8*132];
            aH[m][2]=xHi[r0+4]; aH[m][3]=xHi[r0+8*132+4];
            aL[m][0]=xLo[r0]; aL[m][1]=xLo[r0+8*132];
            aL[m][2]=xLo[r0+4]; aL[m][3]=xLo[r0+8*132+4];
        }
#pragma unroll
        for (int n=0;n<4;n++) {
            int rb = (nOffW + n*8 + g)*132 + k0 + t4;
            b[n][0]=wS[rb]; b[n][1]=wS[rb+4];
        }
#pragma unroll
        for (int m=0;m<2;m++)
#pragma unroll
        for (int n=0;n<4;n++) {
            MMA_TF32(acc[m][n], aL[m], b[n]);
            MMA_TF32(acc[m][n], aH[m], b[n]);
        }
    }
    float stS[8]={0,0,0,0,0,0,0,0}, stQ[8]={0,0,0,0,0,0,0,0};
#pragma unroll
    for (int m=0;m<2;m++)
#pragma unroll
    for (int n=0;n<4;n++) {
        int row = base + sOffW + m*16 + g;
        int col = nOffW + n*8 + 2*t4;
        *(float2*)&dst[(size_t)row*OUTC + col]     = make_float2(acc[m][n][0], acc[m][n][1]);
        *(float2*)&dst[(size_t)(row+8)*OUTC + col] = make_float2(acc[m][n][2], acc[m][n][3]);
        stS[n*2  ] += acc[m][n][0] + acc[m][n][2];
        stS[n*2+1] += acc[m][n][1] + acc[m][n][3];
        stQ[n*2  ] = fmaf(acc[m][n][0],acc[m][n][0], fmaf(acc[m][n][2],acc[m][n][2], stQ[n*2  ]));
        stQ[n*2+1] = fmaf(acc[m][n][1],acc[m][n][1], fmaf(acc[m][n][3],acc[m][n][3], stQ[n*2+1]));
    }
#pragma unroll
    for (int n=0;n<4;n++)
#pragma unroll
    for (int p=0;p<2;p++) {
        int col = nOffW + n*8 + 2*t4 + p;
        atomicAdd(&ssS[col], stS[n*2+p]);
        atomicAdd(&sqS[col], stQ[n*2+p]);
    }
    __syncthreads();
    if (tid < 128) {
        atomicAdd(&d_stats[slot_out*256 + tid],       ssS[tid]);
        atomicAdd(&d_stats[slot_out*256 + 128 + tid], sqS[tid]);
    }
}

// ------- out = relu(bn(h2) + agg) ---------------------------------------------
__global__ void final_kernel(float* __restrict__ out) {
    __shared__ float mS[128], rS[128];
    int tid = threadIdx.x;
    if (tid < 128) {
        float m = d_stats[7*256+tid]*INV_P;
        float v = d_stats[7*256+128+tid]*INV_P - m*m;
        mS[tid]=m; rS[tid]=rsqrtf(v+1e-5f);
    }
    __syncthreads();
    for (int t = blockIdx.x*256 + tid; t < P_TOT*32; t += gridDim.x*256) {
        int q = t & 31, c = q*4;
        float4 h = ((const float4*)g_h2)[t];
        float4 a = ((const float4*)g_agg)[t];
        float4 o;
        o.x = fmaxf((h.x-mS[c  ])*rS[c  ] + a.x, 0.f);
        o.y = fmaxf((h.y-mS[c+1])*rS[c+1] + a.y, 0.f);
        o.z = fmaxf((h.z-mS[c+2])*rS[c+2] + a.z, 0.f);
        o.w = fmaxf((h.w-mS[c+3])*rS[c+3] + a.w, 0.f);
        ((float4*)out)[t] = o;
    }
}

// ------------------------------ launch ----------------------------------------
extern "C" void kernel_launch(void* const* d_in, const int* in_sizes, int n_in,
                              void* d_out, int out_size) {
    const float* xyz     = (const float*)d_in[0];
    const float* feat    = (const float*)d_in[1];
    const float* w_lse1  = (const float*)d_in[2];
    const float* w_lse2  = (const float*)d_in[3];
    const float* ap1_sw1 = (const float*)d_in[4];
    const float* ap1_sw2 = (const float*)d_in[5];
    const float* ap1_mw  = (const float*)d_in[7];
    const float* ap2_sw1 = (const float*)d_in[8];
    const float* ap2_sw2 = (const float*)d_in[9];
    const float* ap2_mw  = (const float*)d_in[11];
    const float* drb_w1  = (const float*)d_in[12];
    const float* drb_w2  = (const float*)d_in[13];
    float* out = (float*)d_out;

    size_t drb_smem = (size_t)(3*128*132) * 4;            // 198 KB
    cudaFuncSetAttribute(drb_mma_kernel, cudaFuncAttributeMaxDynamicSharedMemorySize, (int)drb_smem);

    __half *py1, *py2, *pz1, *pz2;
    float *pg1, *pg2, *ph1, *ph2;
    cudaGetSymbolAddress((void**)&py1, g_y1);
    cudaGetSymbolAddress((void**)&py2, g_y2);
    cudaGetSymbolAddress((void**)&pz1, g_z1);
    cudaGetSymbolAddress((void**)&pz2, g_z2);
    cudaGetSymbolAddress((void**)&pg1, g_g1);
    cudaGetSymbolAddress((void**)&pg2, g_g2);
    cudaGetSymbolAddress((void**)&ph1, g_h1);
    cudaGetSymbolAddress((void**)&ph2, g_h2);

    zero_stats_kernel<<<8,256>>>();
    knn_kernel<<<dim3(Nn/KNN_T, Bz), KNN_T>>>(xyz);
    lse_mma_kernel<<<512,256>>>(xyz, feat, w_lse1, w_lse2, py1, py2);
    xz_mma_kernel<<<dim3(512,2),256>>>(py1, py2, pz1, pz2, ap1_sw1, ap2_sw1);
    pool_kernel<<<dim3(512,2),256>>>(py1, pz1, pg1, ap1_sw2, ap1_mw,
                                     py2, pz2, pg2, ap2_sw2, ap2_mw);
    drb_mma_kernel<<<256,512,drb_smem>>>(pg1, pg2, ph1, drb_w1, 0);
    drb_mma_kernel<<<256,512,drb_smem>>>(ph1, ph1, ph2, drb_w2, 1);
    final_kernel<<<512,256>>>(out);
}